// round 1
// baseline (speedup 1.0000x reference)
#include <cuda_runtime.h>
#include <cstddef>

// ---------------------------------------------------------------------------
// MultiHeadedAttentionWithCache
//   B=16, Q=16, D=1024, H=16, DH=64, C=4096, K-len = 4112
//   out   = [B,Q,D]            (262144 f32)
//   k_up  = [B,H,4112,64]      (67371008 f32)
//   v_up  = [B,H,4112,64]      (67371008 f32)
//   d_out = concat(out, k_up, v_up)
// ---------------------------------------------------------------------------

#define Bdim 16
#define Qdim 16
#define Ddim 1024
#define Hdim 16
#define DH   64
#define Cdim 4096
#define KLEN 4112
#define ROWS 256          // B*Q

// scratch (allocation-free rule: device globals)
__device__ float g_q_heads[ROWS * Ddim];   // [B,H,Q,DH] = [(bh*16+q)*64+dh]
__device__ float g_attn_x[ROWS * Ddim];    // [B,Q,H*DH]

// ---------------------------------------------------------------------------
// Projection GEMM: A[256,1024] @ W[1024,1024] + bias
// mode m: 0=query->g_q_heads (head split), 1=key->k_up tail, 2=value->v_up tail,
//         3=g_attn_x->out
// ---------------------------------------------------------------------------
#define BM 64
#define BN 64
#define BK 16

__global__ void __launch_bounds__(256)
proj_kernel(const float* __restrict__ Aq, const float* __restrict__ Ak,
            const float* __restrict__ Av,
            const float* __restrict__ Wq, const float* __restrict__ Wk,
            const float* __restrict__ Wv,
            const float* __restrict__ bq, const float* __restrict__ bk,
            const float* __restrict__ bv,
            float* __restrict__ dstq,           // out buffer when mode_base=3
            float* __restrict__ k_up, float* __restrict__ v_up,
            int mode_base)
{
    const int m = mode_base ? 3 : (int)blockIdx.z;
    const float* A    = (m == 0) ? Aq : (m == 1) ? Ak : (m == 2) ? Av : g_attn_x;
    const float* W    = (m == 1) ? Wk : (m == 2) ? Wv : Wq;
    const float* bias = (m == 1) ? bk : (m == 2) ? bv : bq;

    __shared__ float As[BK][BM + 4];   // stride 68 floats = 272B (16B-divisible)
    __shared__ float Bs[BK][BN];

    const int rowBase = blockIdx.x * BM;   // grid.x = 4
    const int colBase = blockIdx.y * BN;   // grid.y = 16

    const int t  = threadIdx.x;
    const int tx = t & 15;
    const int ty = t >> 4;

    float acc[4][4];
#pragma unroll
    for (int i = 0; i < 4; i++)
#pragma unroll
        for (int j = 0; j < 4; j++) acc[i][j] = 0.f;

    const int la_r  = t & 63;          // A-tile row
    const int la_k4 = (t >> 6) * 4;    // A-tile k offset (float4)
    const int lb_k  = t >> 4;          // B-tile k row
    const int lb_c4 = (t & 15) * 4;    // B-tile col offset (float4)

    for (int kt = 0; kt < Ddim; kt += BK) {
        float4 a4 = *(const float4*)&A[(size_t)(rowBase + la_r) * Ddim + kt + la_k4];
        As[la_k4 + 0][la_r] = a4.x;
        As[la_k4 + 1][la_r] = a4.y;
        As[la_k4 + 2][la_r] = a4.z;
        As[la_k4 + 3][la_r] = a4.w;
        *(float4*)&Bs[lb_k][lb_c4] =
            *(const float4*)&W[(size_t)(kt + lb_k) * Ddim + colBase + lb_c4];
        __syncthreads();
#pragma unroll
        for (int kk = 0; kk < BK; kk++) {
            float ar[4], br[4];
            *(float4*)ar = *(const float4*)&As[kk][ty * 4];
            *(float4*)br = *(const float4*)&Bs[kk][tx * 4];
#pragma unroll
            for (int i = 0; i < 4; i++)
#pragma unroll
                for (int j = 0; j < 4; j++)
                    acc[i][j] += ar[i] * br[j];
        }
        __syncthreads();
    }

#pragma unroll
    for (int i = 0; i < 4; i++) {
        const int row = rowBase + ty * 4 + i;
        const int b   = row >> 4;
        const int qi  = row & 15;
#pragma unroll
        for (int j = 0; j < 4; j++) {
            const int col = colBase + tx * 4 + j;
            const float val = acc[i][j] + bias[col];
            const int h  = col >> 6;
            const int dh = col & 63;
            if (m == 0) {
                g_q_heads[(size_t)((b * Hdim + h) * Qdim + qi) * DH + dh] = val;
            } else if (m == 1) {
                k_up[((size_t)(b * Hdim + h) * KLEN + Cdim + qi) * DH + dh] = val;
            } else if (m == 2) {
                v_up[((size_t)(b * Hdim + h) * KLEN + Cdim + qi) * DH + dh] = val;
            } else {
                dstq[(size_t)row * Ddim + col] = val;
            }
        }
    }
}

// ---------------------------------------------------------------------------
// Fused attention + cache copy. One block per (b,h). 256 threads.
// Online softmax over KV chunks of 64 rows (64 cache chunks + 1 tail of 16).
// While streaming cache_k/cache_v through smem, the same float4 is STG'd to
// k_up/v_up (fused copy — cache is read exactly once).
// ---------------------------------------------------------------------------
__global__ void __launch_bounds__(256)
attn_kernel(const float* __restrict__ cache_k, const float* __restrict__ cache_v,
            const int* __restrict__ mask,
            float* __restrict__ k_up, float* __restrict__ v_up)
{
    const int bh = blockIdx.x;
    const int b  = bh >> 4;

    __shared__ float Qst[64][16];    // [kk][q], pre-scaled by 1/8
    __shared__ float Kt[64][65];     // [kk][j]
    __shared__ float Vs[64][68];     // [j][dh]
    __shared__ float Ss[16][64];     // scores -> probabilities
    __shared__ int   Ms[16][64];     // mask chunk

    const int t = threadIdx.x;

    // load + scale Q (1/sqrt(64) = 0.125)
    for (int i = t; i < Qdim * DH; i += 256) {
        const int q  = i >> 6;
        const int kk = i & 63;
        Qst[kk][q] = g_q_heads[(size_t)(bh * Qdim + q) * DH + kk] * 0.125f;
    }

    const int row    = t >> 4;        // q index owned in softmax/PV phases
    const int lane16 = t & 15;
    const int dh0    = lane16 * 4;

    float m_i = -1e30f, l_i = 0.f;
    float acc0 = 0.f, acc1 = 0.f, acc2 = 0.f, acc3 = 0.f;

    const float* Kb = cache_k + (size_t)bh * Cdim * DH;
    const float* Vb = cache_v + (size_t)bh * Cdim * DH;
    float* Kout = k_up + (size_t)bh * KLEN * DH;
    float* Vout = v_up + (size_t)bh * KLEN * DH;
    const int* Mb = mask + (size_t)b * Qdim * KLEN;

    const int lj  = t >> 2;          // 0..63 row within chunk
    const int lk0 = (t & 3) * 16;    // 0,16,32,48

    for (int c = 0; c < 65; c++) {
        const int kvBase = c * 64;
        const int cb = (c < 64) ? 64 : 16;

        __syncthreads();   // smem reuse from previous iteration

        if (c < 64) {
#pragma unroll
            for (int e = 0; e < 4; e++) {
                const int kk = lk0 + e * 4;
                const size_t off = (size_t)(kvBase + lj) * DH + kk;
                float4 kv = *(const float4*)&Kb[off];
                *(float4*)&Kout[off] = kv;              // fused cache copy
                Kt[kk + 0][lj] = kv.x; Kt[kk + 1][lj] = kv.y;
                Kt[kk + 2][lj] = kv.z; Kt[kk + 3][lj] = kv.w;
                float4 vv = *(const float4*)&Vb[off];
                *(float4*)&Vout[off] = vv;              // fused cache copy
                *(float4*)&Vs[lj][kk] = vv;
            }
        } else if (lj < 16) {
            // tail rows come from k_up/v_up tail written by proj_kernel
#pragma unroll
            for (int e = 0; e < 4; e++) {
                const int kk = lk0 + e * 4;
                const size_t off = (size_t)(Cdim + lj) * DH + kk;
                float4 kv = *(const float4*)&Kout[off];
                Kt[kk + 0][lj] = kv.x; Kt[kk + 1][lj] = kv.y;
                Kt[kk + 2][lj] = kv.z; Kt[kk + 3][lj] = kv.w;
                *(float4*)&Vs[lj][kk] = *(const float4*)&Vout[off];
            }
        }
        // mask chunk (j >= cb forced to 0 => score -1e9 => p=0)
        for (int i = t; i < Qdim * 64; i += 256) {
            const int q = i >> 6;
            const int j = i & 63;
            Ms[q][j] = (j < cb) ? Mb[q * KLEN + kvBase + j] : 0;
        }
        __syncthreads();

        // --- scores: thread computes 4 queries x 1 key ---
        {
            const int j  = t & 63;
            const int q0 = (t >> 6) * 4;
            float s0 = 0.f, s1 = 0.f, s2 = 0.f, s3 = 0.f;
#pragma unroll 16
            for (int kk = 0; kk < 64; kk++) {
                const float kv = Kt[kk][j];
                float4 qv = *(const float4*)&Qst[kk][q0];
                s0 += qv.x * kv; s1 += qv.y * kv;
                s2 += qv.z * kv; s3 += qv.w * kv;
            }
            Ss[q0 + 0][j] = s0; Ss[q0 + 1][j] = s1;
            Ss[q0 + 2][j] = s2; Ss[q0 + 3][j] = s3;
        }
        __syncthreads();

        // --- online softmax: 16 threads per row ---
        float sv[4];
        float mx = -1e30f;
#pragma unroll
        for (int e = 0; e < 4; e++) {
            const int j = lane16 + e * 16;
            float s = Ss[row][j];
            if (Ms[row][j] == 0) s = -1e9f;
            sv[e] = s;
            mx = fmaxf(mx, s);
        }
#pragma unroll
        for (int off = 8; off; off >>= 1)
            mx = fmaxf(mx, __shfl_xor_sync(0xffffffffu, mx, off));
        const float m_new = fmaxf(m_i, mx);
        const float corr  = __expf(m_i - m_new);
        float lsum = 0.f;
#pragma unroll
        for (int e = 0; e < 4; e++) {
            const float p = __expf(sv[e] - m_new);
            Ss[row][lane16 + e * 16] = p;
            lsum += p;
        }
#pragma unroll
        for (int off = 8; off; off >>= 1)
            lsum += __shfl_xor_sync(0xffffffffu, lsum, off);
        l_i = l_i * corr + lsum;
        m_i = m_new;
        acc0 *= corr; acc1 *= corr; acc2 *= corr; acc3 *= corr;
        __syncthreads();

        // --- PV: acc[dh0..dh0+3] += sum_j p[row][j] * V[j][dh0..] ---
#pragma unroll 8
        for (int j = 0; j < 64; j++) {
            const float p = Ss[row][j];
            float4 v = *(const float4*)&Vs[j][dh0];
            acc0 += p * v.x; acc1 += p * v.y;
            acc2 += p * v.z; acc3 += p * v.w;
        }
    }

    const float inv = 1.f / l_i;
    const int h = bh & 15;
    float4 o = make_float4(acc0 * inv, acc1 * inv, acc2 * inv, acc3 * inv);
    *(float4*)&g_attn_x[(size_t)(b * Qdim + row) * Ddim + h * DH + dh0] = o;
}

// ---------------------------------------------------------------------------
extern "C" void kernel_launch(void* const* d_in, const int* in_sizes, int n_in,
                              void* d_out, int out_size)
{
    const float* query   = (const float*)d_in[0];
    const float* key     = (const float*)d_in[1];
    const float* value   = (const float*)d_in[2];
    const int*   mask    = (const int*)d_in[3];
    const float* cache_k = (const float*)d_in[4];
    const float* cache_v = (const float*)d_in[5];
    const float* Wq = (const float*)d_in[6];
    const float* bq = (const float*)d_in[7];
    const float* Wk = (const float*)d_in[8];
    const float* bk = (const float*)d_in[9];
    const float* Wv = (const float*)d_in[10];
    const float* bv = (const float*)d_in[11];
    const float* Wo = (const float*)d_in[12];
    const float* bo = (const float*)d_in[13];

    float* out  = (float*)d_out;
    float* k_up = out + (size_t)Bdim * Qdim * Ddim;
    float* v_up = k_up + (size_t)Bdim * Hdim * KLEN * DH;

    // 1) QKV projections: q -> scratch heads, k/v -> tails of k_up/v_up
    proj_kernel<<<dim3(4, 16, 3), 256>>>(query, key, value,
                                         Wq, Wk, Wv, bq, bk, bv,
                                         nullptr, k_up, v_up, 0);

    // 2) fused attention + cache copy
    attn_kernel<<<Bdim * Hdim, 256>>>(cache_k, cache_v, mask, k_up, v_up);

    // 3) output projection
    proj_kernel<<<dim3(4, 16, 1), 256>>>(nullptr, nullptr, nullptr,
                                         Wo, nullptr, nullptr,
                                         bo, nullptr, nullptr,
                                         out, k_up, v_up, 3);
}

// round 3
// speedup vs baseline: 1.2300x; 1.2300x over previous
#include <cuda_runtime.h>
#include <cstddef>

// ---------------------------------------------------------------------------
// MultiHeadedAttentionWithCache  (B=16,Q=16,D=1024,H=16,DH=64,C=4096,KLEN=4112)
// d_out = concat(out[16,16,1024], k_up[16,16,4112,64], v_up[16,16,4112,64])
// ---------------------------------------------------------------------------

#define Bdim 16
#define Qdim 16
#define Ddim 1024
#define Hdim 16
#define DH   64
#define Cdim 4096
#define KLEN 4112
#define ROWS 256
#define NSPLIT 4

// scratch (device globals — allocation-free rule)
__device__ float  g_q_heads[ROWS * Ddim];                  // [bh][q][dh]
__device__ float  g_attn_x[ROWS * Ddim];                   // [b*q][h*dh]
__device__ float  g_part_acc[256 * NSPLIT * Qdim * DH];    // [bh][s][q][dh]
__device__ float2 g_part_ml[256 * NSPLIT * Qdim];          // (m, l)

// ---------------------------------------------------------------------------
// Projection GEMM: A[256,1024] @ W[1024,1024] + bias.  32x64 tiles, 384 blocks.
// mode: 0=q->g_q_heads, 1=k->k_up tail, 2=v->v_up tail, 3=g_attn_x->out
// ---------------------------------------------------------------------------
#define BM 32
#define BN 64
#define BK 16

__global__ void __launch_bounds__(256)
proj_kernel(const float* __restrict__ Aq, const float* __restrict__ Ak,
            const float* __restrict__ Av,
            const float* __restrict__ Wq, const float* __restrict__ Wk,
            const float* __restrict__ Wv,
            const float* __restrict__ bq, const float* __restrict__ bk,
            const float* __restrict__ bv,
            float* __restrict__ dstq,
            float* __restrict__ k_up, float* __restrict__ v_up,
            int mode_base)
{
    const int m = mode_base ? 3 : (int)blockIdx.z;
    const float* A    = (m == 0) ? Aq : (m == 1) ? Ak : (m == 2) ? Av : g_attn_x;
    const float* W    = (m == 1) ? Wk : (m == 2) ? Wv : Wq;
    const float* bias = (m == 1) ? bk : (m == 2) ? bv : bq;

    __shared__ float As[BK][BM + 2];   // stride 34 floats (8B-aligned rows)
    __shared__ float Bs[BK][BN];

    const int rowBase = blockIdx.x * BM;   // grid.x = 8
    const int colBase = blockIdx.y * BN;   // grid.y = 16

    const int t  = threadIdx.x;
    const int tx = t & 15;
    const int ty = t >> 4;

    float acc[2][4];
#pragma unroll
    for (int i = 0; i < 2; i++)
#pragma unroll
        for (int j = 0; j < 4; j++) acc[i][j] = 0.f;

    const int la_r  = t >> 3;          // 0..31
    const int la_k  = (t & 7) * 2;     // 0..14
    const int lb_k  = t >> 4;
    const int lb_c4 = (t & 15) * 4;

    for (int kt = 0; kt < Ddim; kt += BK) {
        float2 a2 = *(const float2*)&A[(size_t)(rowBase + la_r) * Ddim + kt + la_k];
        As[la_k + 0][la_r] = a2.x;
        As[la_k + 1][la_r] = a2.y;
        *(float4*)&Bs[lb_k][lb_c4] =
            *(const float4*)&W[(size_t)(kt + lb_k) * Ddim + colBase + lb_c4];
        __syncthreads();
#pragma unroll
        for (int kk = 0; kk < BK; kk++) {
            float2 ar = *(const float2*)&As[kk][ty * 2];
            float4 br = *(const float4*)&Bs[kk][tx * 4];
            acc[0][0] += ar.x * br.x; acc[0][1] += ar.x * br.y;
            acc[0][2] += ar.x * br.z; acc[0][3] += ar.x * br.w;
            acc[1][0] += ar.y * br.x; acc[1][1] += ar.y * br.y;
            acc[1][2] += ar.y * br.z; acc[1][3] += ar.y * br.w;
        }
        __syncthreads();
    }

#pragma unroll
    for (int i = 0; i < 2; i++) {
        const int row = rowBase + ty * 2 + i;
        const int b   = row >> 4;
        const int qi  = row & 15;
#pragma unroll
        for (int j = 0; j < 4; j++) {
            const int col = colBase + tx * 4 + j;
            const float val = acc[i][j] + bias[col];
            const int h  = col >> 6;
            const int dh = col & 63;
            if (m == 0) {
                g_q_heads[(size_t)((b * Hdim + h) * Qdim + qi) * DH + dh] = val;
            } else if (m == 1) {
                k_up[((size_t)(b * Hdim + h) * KLEN + Cdim + qi) * DH + dh] = val;
            } else if (m == 2) {
                v_up[((size_t)(b * Hdim + h) * KLEN + Cdim + qi) * DH + dh] = val;
            } else {
                dstq[(size_t)row * Ddim + col] = val;
            }
        }
    }
}

// ---------------------------------------------------------------------------
// Split-K fused attention + cache copy. 1024 blocks = (bh, split of 4).
// Register-double-buffered 64-row KV chunks; packed f32x2 FMA; partial
// (m, l, acc) written for the combine kernel.
// ---------------------------------------------------------------------------
__global__ void __launch_bounds__(256)
attn_kernel(const float* __restrict__ cache_k, const float* __restrict__ cache_v,
            const int* __restrict__ mask,
            float* __restrict__ k_up, float* __restrict__ v_up)
{
    const int blk   = blockIdx.x;
    const int bh    = blk >> 2;
    const int split = blk & 3;
    const int b     = bh >> 4;

    // 65 chunks (64 full + 16-row tail) over 4 splits: 17,16,16,16
    const int cStart = (split == 0) ? 0 : 17 + 16 * (split - 1);
    const int cEnd   = (split == 3) ? 65 : 17 + 16 * split;

    __shared__ float Qst[64][16];    // [kk][q], pre-scaled by 1/8
    __shared__ float Kt[64][65];     // [kk][j]
    __shared__ float Vs[64][68];     // [j][dh]
    __shared__ float Ss[16][64];     // scores -> probabilities

    const int t = threadIdx.x;

    for (int i = t; i < Qdim * DH; i += 256) {
        const int q  = i >> 6;
        const int kk = i & 63;
        Qst[kk][q] = g_q_heads[(size_t)(bh * Qdim + q) * DH + kk] * 0.125f;
    }

    const int row    = t >> 4;
    const int lane16 = t & 15;
    const int dh0    = lane16 * 4;
    const int lj     = t >> 2;          // 0..63
    const int lk0    = (t & 3) * 16;

    float m_i = -1e30f, l_i = 0.f;
    unsigned long long a01 = 0ull, a23 = 0ull;   // packed f32x2 accumulators

    const float* Kb = cache_k + (size_t)bh * Cdim * DH;
    const float* Vb = cache_v + (size_t)bh * Cdim * DH;
    float* Kout = k_up + (size_t)bh * KLEN * DH;
    float* Vout = v_up + (size_t)bh * KLEN * DH;
    const int* Mb = mask + (size_t)b * Qdim * KLEN;

    float4 kf[4], vf[4];   // register double-buffer

    auto prefetch_kv = [&](int c) {
        if (c < 64) {
#pragma unroll
            for (int e = 0; e < 4; e++) {
                const size_t off = ((size_t)(c * 64 + lj)) * DH + lk0 + e * 4;
                kf[e] = *(const float4*)&Kb[off];
                vf[e] = *(const float4*)&Vb[off];
            }
        } else if (lj < 16) {
            // tail rows already projected into k_up/v_up tail
#pragma unroll
            for (int e = 0; e < 4; e++) {
                const size_t off = ((size_t)(Cdim + lj)) * DH + lk0 + e * 4;
                kf[e] = *(const float4*)&Kout[off];
                vf[e] = *(const float4*)&Vout[off];
            }
        }
    };

    prefetch_kv(cStart);

    for (int c = cStart; c < cEnd; c++) {
        const int kvBase = c * 64;
        const bool full  = (c < 64);

        __syncthreads();   // previous PV done with Vs/Ss

        // commit prefetched chunk to smem (+ fused gmem cache copy)
        if (full) {
#pragma unroll
            for (int e = 0; e < 4; e++) {
                const int kk = lk0 + e * 4;
                const size_t off = ((size_t)(kvBase + lj)) * DH + kk;
                *(float4*)&Kout[off] = kf[e];
                *(float4*)&Vout[off] = vf[e];
                Kt[kk + 0][lj] = kf[e].x; Kt[kk + 1][lj] = kf[e].y;
                Kt[kk + 2][lj] = kf[e].z; Kt[kk + 3][lj] = kf[e].w;
                *(float4*)&Vs[lj][kk] = vf[e];
            }
        } else if (lj < 16) {
#pragma unroll
            for (int e = 0; e < 4; e++) {
                const int kk = lk0 + e * 4;
                Kt[kk + 0][lj] = kf[e].x; Kt[kk + 1][lj] = kf[e].y;
                Kt[kk + 2][lj] = kf[e].z; Kt[kk + 3][lj] = kf[e].w;
                *(float4*)&Vs[lj][kk] = vf[e];
            }
        }
        __syncthreads();

        // mask for this chunk (registers; consumed in softmax — latency hidden)
        int mcur[4];
        const int cb = full ? 64 : 16;
#pragma unroll
        for (int e = 0; e < 4; e++) {
            const int j = lane16 + e * 16;
            mcur[e] = (j < cb) ? Mb[row * KLEN + kvBase + j] : 0;
        }

        // prefetch next chunk (overlaps with compute below)
        if (c + 1 < cEnd) prefetch_kv(c + 1);

        // --- scores: thread = (4 queries, 1 key), packed FFMA2 ---
        {
            const int j  = t & 63;
            const int q0 = (t >> 6) * 4;
            unsigned long long s01 = 0ull, s23 = 0ull;
#pragma unroll 16
            for (int kk = 0; kk < 64; kk++) {
                const float kv = Kt[kk][j];
                unsigned long long kv2;
                asm("mov.b64 %0, {%1, %1};" : "=l"(kv2) : "f"(kv));
                ulonglong2 qq = *reinterpret_cast<const ulonglong2*>(&Qst[kk][q0]);
                asm("fma.rn.f32x2 %0, %1, %2, %0;" : "+l"(s01) : "l"(qq.x), "l"(kv2));
                asm("fma.rn.f32x2 %0, %1, %2, %0;" : "+l"(s23) : "l"(qq.y), "l"(kv2));
            }
            float f0, f1, f2, f3;
            asm("mov.b64 {%0, %1}, %2;" : "=f"(f0), "=f"(f1) : "l"(s01));
            asm("mov.b64 {%0, %1}, %2;" : "=f"(f2), "=f"(f3) : "l"(s23));
            Ss[q0 + 0][j] = f0; Ss[q0 + 1][j] = f1;
            Ss[q0 + 2][j] = f2; Ss[q0 + 3][j] = f3;
        }
        __syncthreads();

        // --- online softmax: 16 threads per query row ---
        float sv[4];
        float mx = -1e30f;
#pragma unroll
        for (int e = 0; e < 4; e++) {
            float s = Ss[row][lane16 + e * 16];
            if (mcur[e] == 0) s = -1e9f;
            sv[e] = s;
            mx = fmaxf(mx, s);
        }
#pragma unroll
        for (int off = 8; off; off >>= 1)
            mx = fmaxf(mx, __shfl_xor_sync(0xffffffffu, mx, off));
        const float m_new = fmaxf(m_i, mx);
        const float corr  = __expf(m_i - m_new);
        float lsum = 0.f;
#pragma unroll
        for (int e = 0; e < 4; e++) {
            const float p = __expf(sv[e] - m_new);
            Ss[row][lane16 + e * 16] = p;
            lsum += p;
        }
#pragma unroll
        for (int off = 8; off; off >>= 1)
            lsum += __shfl_xor_sync(0xffffffffu, lsum, off);
        l_i = l_i * corr + lsum;
        m_i = m_new;
        unsigned long long corr2;
        asm("mov.b64 %0, {%1, %1};" : "=l"(corr2) : "f"(corr));
        asm("mul.rn.f32x2 %0, %0, %1;" : "+l"(a01) : "l"(corr2));
        asm("mul.rn.f32x2 %0, %0, %1;" : "+l"(a23) : "l"(corr2));
        __syncwarp();   // Ss row written & read by same half-warp

        // --- PV: packed FFMA2 over 64 keys ---
#pragma unroll 8
        for (int j = 0; j < 64; j++) {
            const float p = Ss[row][j];
            unsigned long long p2;
            asm("mov.b64 %0, {%1, %1};" : "=l"(p2) : "f"(p));
            ulonglong2 vv = *reinterpret_cast<const ulonglong2*>(&Vs[j][dh0]);
            asm("fma.rn.f32x2 %0, %1, %2, %0;" : "+l"(a01) : "l"(vv.x), "l"(p2));
            asm("fma.rn.f32x2 %0, %1, %2, %0;" : "+l"(a23) : "l"(vv.y), "l"(p2));
        }
    }

    // store unnormalized partials + (m, l)
    float o0, o1, o2, o3;
    asm("mov.b64 {%0, %1}, %2;" : "=f"(o0), "=f"(o1) : "l"(a01));
    asm("mov.b64 {%0, %1}, %2;" : "=f"(o2), "=f"(o3) : "l"(a23));
    const size_t pbase = ((size_t)(bh * NSPLIT + split) * Qdim + row) * DH + dh0;
    float4 o = make_float4(o0, o1, o2, o3);
    *(float4*)&g_part_acc[pbase] = o;
    if (lane16 == 0)
        g_part_ml[(bh * NSPLIT + split) * Qdim + row] = make_float2(m_i, l_i);
}

// ---------------------------------------------------------------------------
// Combine split-K partials -> g_attn_x
// ---------------------------------------------------------------------------
__global__ void __launch_bounds__(256)
combine_kernel()
{
    const int bh  = blockIdx.x;
    const int t   = threadIdx.x;
    const int row = t >> 4;
    const int dh0 = (t & 15) * 4;

    float2 ml[NSPLIT];
    float m = -1e30f;
#pragma unroll
    for (int s = 0; s < NSPLIT; s++) {
        ml[s] = g_part_ml[(bh * NSPLIT + s) * Qdim + row];
        m = fmaxf(m, ml[s].x);
    }
    float l = 0.f;
    float4 o = make_float4(0.f, 0.f, 0.f, 0.f);
#pragma unroll
    for (int s = 0; s < NSPLIT; s++) {
        const float w = __expf(ml[s].x - m);
        l += ml[s].y * w;
        float4 a = *(const float4*)&g_part_acc[((size_t)(bh * NSPLIT + s) * Qdim + row) * DH + dh0];
        o.x += a.x * w; o.y += a.y * w; o.z += a.z * w; o.w += a.w * w;
    }
    const float inv = 1.f / l;
    const int b = bh >> 4;
    const int h = bh & 15;
    o.x *= inv; o.y *= inv; o.z *= inv; o.w *= inv;
    *(float4*)&g_attn_x[(size_t)(b * Qdim + row) * Ddim + h * DH + dh0] = o;
}

// ---------------------------------------------------------------------------
extern "C" void kernel_launch(void* const* d_in, const int* in_sizes, int n_in,
                              void* d_out, int out_size)
{
    const float* query   = (const float*)d_in[0];
    const float* key     = (const float*)d_in[1];
    const float* value   = (const float*)d_in[2];
    const int*   mask    = (const int*)d_in[3];
    const float* cache_k = (const float*)d_in[4];
    const float* cache_v = (const float*)d_in[5];
    const float* Wq = (const float*)d_in[6];
    const float* bq = (const float*)d_in[7];
    const float* Wk = (const float*)d_in[8];
    const float* bk = (const float*)d_in[9];
    const float* Wv = (const float*)d_in[10];
    const float* bv = (const float*)d_in[11];
    const float* Wo = (const float*)d_in[12];
    const float* bo = (const float*)d_in[13];

    float* out  = (float*)d_out;
    float* k_up = out + (size_t)Bdim * Qdim * Ddim;
    float* v_up = k_up + (size_t)Bdim * Hdim * KLEN * DH;

    proj_kernel<<<dim3(8, 16, 3), 256>>>(query, key, value,
                                         Wq, Wk, Wv, bq, bk, bv,
                                         nullptr, k_up, v_up, 0);

    attn_kernel<<<Bdim * Hdim * NSPLIT, 256>>>(cache_k, cache_v, mask, k_up, v_up);

    combine_kernel<<<Bdim * Hdim, 256>>>();

    proj_kernel<<<dim3(8, 16, 1), 256>>>(nullptr, nullptr, nullptr,
                                         Wo, nullptr, nullptr,
                                         bo, nullptr, nullptr,
                                         out, k_up, v_up, 3);
}

// round 4
// speedup vs baseline: 1.4016x; 1.1395x over previous
#include <cuda_runtime.h>
#include <cstddef>

// ---------------------------------------------------------------------------
// MultiHeadedAttentionWithCache  (B=16,Q=16,D=1024,H=16,DH=64,C=4096,KLEN=4112)
// d_out = concat(out[16,16,1024], k_up[16,16,4112,64], v_up[16,16,4112,64])
// ---------------------------------------------------------------------------

#define Bdim 16
#define Qdim 16
#define Ddim 1024
#define Hdim 16
#define DH   64
#define Cdim 4096
#define KLEN 4112
#define ROWS 256
#define NSPLIT 8
#define KS 4                      // split-K factor for projections

// scratch (device globals — allocation-free rule)
__device__ float  g_q_heads[ROWS * Ddim];                  // [bh][q][dh]
__device__ float  g_attn_x[ROWS * Ddim];                   // [b*q][h*dh]
__device__ float  g_part_acc[256 * NSPLIT * Qdim * DH];    // [bh][s][q][dh]
__device__ float2 g_part_ml[256 * NSPLIT * Qdim];          // (m, l)
__device__ float  g_proj_part[3 * KS * ROWS * Ddim];       // GEMM split-K partials

// ---------------------------------------------------------------------------
// Projection GEMM, split-K: A[256,1024] @ W[1024,1024], 64x64 tiles,
// each block covers a K-slice of 256. Partials (no bias) -> g_proj_part.
// modes 0..2 fused via blockIdx.z (q,k,v); mode 3 = attn output proj.
// ---------------------------------------------------------------------------
#define BM 64
#define BN 64
#define BK 16

__global__ void __launch_bounds__(256)
proj_kernel(const float* __restrict__ Aq, const float* __restrict__ Ak,
            const float* __restrict__ Av,
            const float* __restrict__ Wq, const float* __restrict__ Wk,
            const float* __restrict__ Wv,
            int mode_base)
{
    const int zz = blockIdx.z;
    const int m  = mode_base ? 3 : (zz / KS);
    const int ks = mode_base ? zz : (zz % KS);
    const int mslot = (m == 3) ? 0 : m;

    const float* A = (m == 0) ? Aq : (m == 1) ? Ak : (m == 2) ? Av : g_attn_x;
    const float* W = (m == 1) ? Wk : (m == 2) ? Wv : Wq;

    __shared__ float As[BK][BM + 4];
    __shared__ float Bs[BK][BN];

    const int rowBase = blockIdx.x * BM;   // grid.x = 4
    const int colBase = blockIdx.y * BN;   // grid.y = 16

    const int t  = threadIdx.x;
    const int tx = t & 15;
    const int ty = t >> 4;

    float acc[4][4];
#pragma unroll
    for (int i = 0; i < 4; i++)
#pragma unroll
        for (int j = 0; j < 4; j++) acc[i][j] = 0.f;

    const int la_r  = t & 63;          // A-tile row
    const int la_k4 = (t >> 6) * 4;    // A-tile k offset (float4)
    const int lb_k  = t >> 4;          // B-tile k row
    const int lb_c4 = (t & 15) * 4;

    const int k0 = ks * (Ddim / KS);

    for (int kt = k0; kt < k0 + Ddim / KS; kt += BK) {
        float4 a4 = *(const float4*)&A[(size_t)(rowBase + la_r) * Ddim + kt + la_k4];
        As[la_k4 + 0][la_r] = a4.x;
        As[la_k4 + 1][la_r] = a4.y;
        As[la_k4 + 2][la_r] = a4.z;
        As[la_k4 + 3][la_r] = a4.w;
        *(float4*)&Bs[lb_k][lb_c4] =
            *(const float4*)&W[(size_t)(kt + lb_k) * Ddim + colBase + lb_c4];
        __syncthreads();
#pragma unroll
        for (int kk = 0; kk < BK; kk++) {
            float ar[4], br[4];
            *(float4*)ar = *(const float4*)&As[kk][ty * 4];
            *(float4*)br = *(const float4*)&Bs[kk][tx * 4];
#pragma unroll
            for (int i = 0; i < 4; i++)
#pragma unroll
                for (int j = 0; j < 4; j++)
                    acc[i][j] += ar[i] * br[j];
        }
        __syncthreads();
    }

    float* P = g_proj_part + (size_t)(mslot * KS + ks) * ROWS * Ddim;
#pragma unroll
    for (int i = 0; i < 4; i++) {
        const int row = rowBase + ty * 4 + i;
#pragma unroll
        for (int j = 0; j < 4; j += 4) {
            float4 v = make_float4(acc[i][0], acc[i][1], acc[i][2], acc[i][3]);
            *(float4*)&P[(size_t)row * Ddim + colBase + tx * 4] = v;
        }
    }
}

// ---------------------------------------------------------------------------
// Combine split-K partials, add bias, scatter per mode.
// grid (ROWS, 3) for modes 0-2; grid (ROWS, 1) with mode_base=1 for mode 3.
// ---------------------------------------------------------------------------
__global__ void __launch_bounds__(256)
combine_proj(const float* __restrict__ bq, const float* __restrict__ bk,
             const float* __restrict__ bv, const float* __restrict__ bo,
             float* __restrict__ out,
             float* __restrict__ k_up, float* __restrict__ v_up,
             int mode_base)
{
    const int m   = mode_base ? 3 : (int)blockIdx.y;
    const int mslot = (m == 3) ? 0 : m;
    const int row = blockIdx.x;          // 0..255
    const int t   = threadIdx.x;         // 256 threads, one float4 each
    const int col = t * 4;

    const float* bias = (m == 1) ? bk : (m == 2) ? bv : (m == 3) ? bo : bq;

    const float* P = g_proj_part + (size_t)(mslot * KS) * ROWS * Ddim
                   + (size_t)row * Ddim + col;
    float4 s = *(const float4*)&P[0];
#pragma unroll
    for (int ksl = 1; ksl < KS; ksl++) {
        float4 p = *(const float4*)&P[(size_t)ksl * ROWS * Ddim];
        s.x += p.x; s.y += p.y; s.z += p.z; s.w += p.w;
    }
    float4 bb = *(const float4*)&bias[col];
    s.x += bb.x; s.y += bb.y; s.z += bb.z; s.w += bb.w;

    const int b  = row >> 4;
    const int qi = row & 15;
    const int h  = col >> 6;
    const int dh = col & 63;

    if (m == 0) {
        *(float4*)&g_q_heads[(size_t)((b * Hdim + h) * Qdim + qi) * DH + dh] = s;
    } else if (m == 1) {
        *(float4*)&k_up[((size_t)(b * Hdim + h) * KLEN + Cdim + qi) * DH + dh] = s;
    } else if (m == 2) {
        *(float4*)&v_up[((size_t)(b * Hdim + h) * KLEN + Cdim + qi) * DH + dh] = s;
    } else {
        *(float4*)&out[(size_t)row * Ddim + col] = s;
    }
}

// ---------------------------------------------------------------------------
// Split-K fused attention + cache copy. 2048 blocks = (bh, split of 8),
// interleaved chunk assignment c = split, split+8, ... (tail chunk 64 -> split 0).
// Register-double-buffered 64-row KV chunks; packed f32x2 FMA.
// ---------------------------------------------------------------------------
__global__ void __launch_bounds__(256)
attn_kernel(const float* __restrict__ cache_k, const float* __restrict__ cache_v,
            const int* __restrict__ mask,
            float* __restrict__ k_up, float* __restrict__ v_up)
{
    const int blk   = blockIdx.x;
    const int bh    = blk >> 3;
    const int split = blk & 7;
    const int b     = bh >> 4;

    __shared__ float Qst[64][16];    // [kk][q], pre-scaled by 1/8
    __shared__ float Kt[64][65];     // [kk][j]
    __shared__ float Vs[64][68];     // [j][dh]
    __shared__ float Ss[16][64];     // scores -> probabilities

    const int t = threadIdx.x;

    for (int i = t; i < Qdim * DH; i += 256) {
        const int q  = i >> 6;
        const int kk = i & 63;
        Qst[kk][q] = g_q_heads[(size_t)(bh * Qdim + q) * DH + kk] * 0.125f;
    }

    const int row    = t >> 4;
    const int lane16 = t & 15;
    const int dh0    = lane16 * 4;
    const int lj     = t >> 2;          // 0..63
    const int lk0    = (t & 3) * 16;

    float m_i = -1e30f, l_i = 0.f;
    unsigned long long a01 = 0ull, a23 = 0ull;

    const float* Kb = cache_k + (size_t)bh * Cdim * DH;
    const float* Vb = cache_v + (size_t)bh * Cdim * DH;
    float* Kout = k_up + (size_t)bh * KLEN * DH;
    float* Vout = v_up + (size_t)bh * KLEN * DH;
    const int* Mb = mask + (size_t)b * Qdim * KLEN;

    float4 kf[4], vf[4];   // register double-buffer

    auto prefetch_kv = [&](int c) {
        if (c < 64) {
#pragma unroll
            for (int e = 0; e < 4; e++) {
                const size_t off = ((size_t)(c * 64 + lj)) * DH + lk0 + e * 4;
                kf[e] = *(const float4*)&Kb[off];
                vf[e] = *(const float4*)&Vb[off];
            }
        } else if (lj < 16) {
            // tail rows already projected into k_up/v_up tail
#pragma unroll
            for (int e = 0; e < 4; e++) {
                const size_t off = ((size_t)(Cdim + lj)) * DH + lk0 + e * 4;
                kf[e] = *(const float4*)&Kout[off];
                vf[e] = *(const float4*)&Vout[off];
            }
        }
    };

    prefetch_kv(split);

    for (int c = split; c < 65; c += NSPLIT) {
        const int kvBase = c * 64;
        const bool full  = (c < 64);

        __syncthreads();   // previous PV done with Vs/Ss

        // commit prefetched chunk to smem (+ fused gmem cache copy)
        if (full) {
#pragma unroll
            for (int e = 0; e < 4; e++) {
                const int kk = lk0 + e * 4;
                const size_t off = ((size_t)(kvBase + lj)) * DH + kk;
                *(float4*)&Kout[off] = kf[e];
                *(float4*)&Vout[off] = vf[e];
                Kt[kk + 0][lj] = kf[e].x; Kt[kk + 1][lj] = kf[e].y;
                Kt[kk + 2][lj] = kf[e].z; Kt[kk + 3][lj] = kf[e].w;
                *(float4*)&Vs[lj][kk] = vf[e];
            }
        } else if (lj < 16) {
#pragma unroll
            for (int e = 0; e < 4; e++) {
                const int kk = lk0 + e * 4;
                Kt[kk + 0][lj] = kf[e].x; Kt[kk + 1][lj] = kf[e].y;
                Kt[kk + 2][lj] = kf[e].z; Kt[kk + 3][lj] = kf[e].w;
                *(float4*)&Vs[lj][kk] = vf[e];
            }
        }
        __syncthreads();

        // mask for this chunk (registers)
        int mcur[4];
        const int cb = full ? 64 : 16;
#pragma unroll
        for (int e = 0; e < 4; e++) {
            const int j = lane16 + e * 16;
            mcur[e] = (j < cb) ? Mb[row * KLEN + kvBase + j] : 0;
        }

        // prefetch next chunk (overlaps with compute below)
        if (c + NSPLIT < 65) prefetch_kv(c + NSPLIT);

        // --- scores: thread = (4 queries, 1 key), packed FFMA2 ---
        {
            const int j  = t & 63;
            const int q0 = (t >> 6) * 4;
            unsigned long long s01 = 0ull, s23 = 0ull;
#pragma unroll 16
            for (int kk = 0; kk < 64; kk++) {
                const float kv = Kt[kk][j];
                unsigned long long kv2;
                asm("mov.b64 %0, {%1, %1};" : "=l"(kv2) : "f"(kv));
                ulonglong2 qq = *reinterpret_cast<const ulonglong2*>(&Qst[kk][q0]);
                asm("fma.rn.f32x2 %0, %1, %2, %0;" : "+l"(s01) : "l"(qq.x), "l"(kv2));
                asm("fma.rn.f32x2 %0, %1, %2, %0;" : "+l"(s23) : "l"(qq.y), "l"(kv2));
            }
            float f0, f1, f2, f3;
            asm("mov.b64 {%0, %1}, %2;" : "=f"(f0), "=f"(f1) : "l"(s01));
            asm("mov.b64 {%0, %1}, %2;" : "=f"(f2), "=f"(f3) : "l"(s23));
            Ss[q0 + 0][j] = f0; Ss[q0 + 1][j] = f1;
            Ss[q0 + 2][j] = f2; Ss[q0 + 3][j] = f3;
        }
        __syncthreads();

        // --- online softmax: 16 threads per query row ---
        float sv[4];
        float mx = -1e30f;
#pragma unroll
        for (int e = 0; e < 4; e++) {
            float s = Ss[row][lane16 + e * 16];
            if (mcur[e] == 0) s = -1e9f;
            sv[e] = s;
            mx = fmaxf(mx, s);
        }
#pragma unroll
        for (int off = 8; off; off >>= 1)
            mx = fmaxf(mx, __shfl_xor_sync(0xffffffffu, mx, off));
        const float m_new = fmaxf(m_i, mx);
        const float corr  = __expf(m_i - m_new);
        float lsum = 0.f;
#pragma unroll
        for (int e = 0; e < 4; e++) {
            const float p = __expf(sv[e] - m_new);
            Ss[row][lane16 + e * 16] = p;
            lsum += p;
        }
#pragma unroll
        for (int off = 8; off; off >>= 1)
            lsum += __shfl_xor_sync(0xffffffffu, lsum, off);
        l_i = l_i * corr + lsum;
        m_i = m_new;
        unsigned long long corr2;
        asm("mov.b64 %0, {%1, %1};" : "=l"(corr2) : "f"(corr));
        asm("mul.rn.f32x2 %0, %0, %1;" : "+l"(a01) : "l"(corr2));
        asm("mul.rn.f32x2 %0, %0, %1;" : "+l"(a23) : "l"(corr2));
        __syncwarp();   // Ss row written & read within the same warp

        // --- PV: packed FFMA2 over 64 keys ---
#pragma unroll 8
        for (int j = 0; j < 64; j++) {
            const float p = Ss[row][j];
            unsigned long long p2;
            asm("mov.b64 %0, {%1, %1};" : "=l"(p2) : "f"(p));
            ulonglong2 vv = *reinterpret_cast<const ulonglong2*>(&Vs[j][dh0]);
            asm("fma.rn.f32x2 %0, %1, %2, %0;" : "+l"(a01) : "l"(vv.x), "l"(p2));
            asm("fma.rn.f32x2 %0, %1, %2, %0;" : "+l"(a23) : "l"(vv.y), "l"(p2));
        }
    }

    // store unnormalized partials + (m, l)
    float o0, o1, o2, o3;
    asm("mov.b64 {%0, %1}, %2;" : "=f"(o0), "=f"(o1) : "l"(a01));
    asm("mov.b64 {%0, %1}, %2;" : "=f"(o2), "=f"(o3) : "l"(a23));
    const size_t pbase = ((size_t)(bh * NSPLIT + split) * Qdim + row) * DH + dh0;
    *(float4*)&g_part_acc[pbase] = make_float4(o0, o1, o2, o3);
    if (lane16 == 0)
        g_part_ml[(bh * NSPLIT + split) * Qdim + row] = make_float2(m_i, l_i);
}

// ---------------------------------------------------------------------------
// Combine attention split partials -> g_attn_x
// ---------------------------------------------------------------------------
__global__ void __launch_bounds__(256)
combine_kernel()
{
    const int bh  = blockIdx.x;
    const int t   = threadIdx.x;
    const int row = t >> 4;
    const int dh0 = (t & 15) * 4;

    float2 ml[NSPLIT];
    float m = -1e30f;
#pragma unroll
    for (int s = 0; s < NSPLIT; s++) {
        ml[s] = g_part_ml[(bh * NSPLIT + s) * Qdim + row];
        m = fmaxf(m, ml[s].x);
    }
    float l = 0.f;
    float4 o = make_float4(0.f, 0.f, 0.f, 0.f);
#pragma unroll
    for (int s = 0; s < NSPLIT; s++) {
        const float w = __expf(ml[s].x - m);
        l += ml[s].y * w;
        float4 a = *(const float4*)&g_part_acc[((size_t)(bh * NSPLIT + s) * Qdim + row) * DH + dh0];
        o.x += a.x * w; o.y += a.y * w; o.z += a.z * w; o.w += a.w * w;
    }
    const float inv = 1.f / l;
    const int b = bh >> 4;
    const int h = bh & 15;
    o.x *= inv; o.y *= inv; o.z *= inv; o.w *= inv;
    *(float4*)&g_attn_x[(size_t)(b * Qdim + row) * Ddim + h * DH + dh0] = o;
}

// ---------------------------------------------------------------------------
extern "C" void kernel_launch(void* const* d_in, const int* in_sizes, int n_in,
                              void* d_out, int out_size)
{
    const float* query   = (const float*)d_in[0];
    const float* key     = (const float*)d_in[1];
    const float* value   = (const float*)d_in[2];
    const int*   mask    = (const int*)d_in[3];
    const float* cache_k = (const float*)d_in[4];
    const float* cache_v = (const float*)d_in[5];
    const float* Wq = (const float*)d_in[6];
    const float* bq = (const float*)d_in[7];
    const float* Wk = (const float*)d_in[8];
    const float* bk = (const float*)d_in[9];
    const float* Wv = (const float*)d_in[10];
    const float* bv = (const float*)d_in[11];
    const float* Wo = (const float*)d_in[12];
    const float* bo = (const float*)d_in[13];

    float* out  = (float*)d_out;
    float* k_up = out + (size_t)Bdim * Qdim * Ddim;
    float* v_up = k_up + (size_t)Bdim * Hdim * KLEN * DH;

    // 1) QKV projections, split-K partials (768 blocks)
    proj_kernel<<<dim3(4, 16, 3 * KS), 256>>>(query, key, value,
                                              Wq, Wk, Wv, 0);
    // 1b) combine + bias + scatter (q heads, k/v tails)
    combine_proj<<<dim3(ROWS, 3), 256>>>(bq, bk, bv, bo, out, k_up, v_up, 0);

    // 2) fused attention + cache copy (2048 blocks)
    attn_kernel<<<Bdim * Hdim * NSPLIT, 256>>>(cache_k, cache_v, mask, k_up, v_up);

    // 2b) combine attention splits
    combine_kernel<<<Bdim * Hdim, 256>>>();

    // 3) output projection, split-K (256 blocks) + combine
    proj_kernel<<<dim3(4, 16, KS), 256>>>(nullptr, nullptr, nullptr,
                                          Wo, nullptr, nullptr, 1);
    combine_proj<<<dim3(ROWS, 1), 256>>>(bq, bk, bv, bo, out, k_up, v_up, 1);
}

// round 5
// speedup vs baseline: 1.4326x; 1.0222x over previous
#include <cuda_runtime.h>
#include <cstddef>

// ---------------------------------------------------------------------------
// MultiHeadedAttentionWithCache  (B=16,Q=16,D=1024,H=16,DH=64,C=4096,KLEN=4112)
// d_out = concat(out[16,16,1024], k_up[16,16,4112,64], v_up[16,16,4112,64])
// ---------------------------------------------------------------------------

#define Bdim 16
#define Qdim 16
#define Ddim 1024
#define Hdim 16
#define DH   64
#define Cdim 4096
#define KLEN 4112
#define ROWS 256
#define NSPLIT 8
#define KS 4                      // split-K factor for projections

// scratch (device globals — allocation-free rule)
__device__ float  g_q_heads[ROWS * Ddim];                  // [bh][q][dh]
__device__ float  g_attn_x[ROWS * Ddim];                   // [b*q][h*dh]
__device__ float  g_part_acc[256 * NSPLIT * Qdim * DH];    // [bh][s][q][dh]
__device__ float2 g_part_ml[256 * NSPLIT * Qdim];          // (m, l)
__device__ float  g_proj_part[3 * KS * ROWS * Ddim];       // GEMM split-K partials

// ---------------------------------------------------------------------------
// Projection GEMM, split-K (unchanged from round 4)
// ---------------------------------------------------------------------------
#define BM 64
#define BN 64
#define BK 16

__global__ void __launch_bounds__(256)
proj_kernel(const float* __restrict__ Aq, const float* __restrict__ Ak,
            const float* __restrict__ Av,
            const float* __restrict__ Wq, const float* __restrict__ Wk,
            const float* __restrict__ Wv,
            int mode_base)
{
    const int zz = blockIdx.z;
    const int m  = mode_base ? 3 : (zz / KS);
    const int ks = mode_base ? zz : (zz % KS);
    const int mslot = (m == 3) ? 0 : m;

    const float* A = (m == 0) ? Aq : (m == 1) ? Ak : (m == 2) ? Av : g_attn_x;
    const float* W = (m == 1) ? Wk : (m == 2) ? Wv : Wq;

    __shared__ float As[BK][BM + 4];
    __shared__ float Bs[BK][BN];

    const int rowBase = blockIdx.x * BM;
    const int colBase = blockIdx.y * BN;

    const int t  = threadIdx.x;
    const int tx = t & 15;
    const int ty = t >> 4;

    float acc[4][4];
#pragma unroll
    for (int i = 0; i < 4; i++)
#pragma unroll
        for (int j = 0; j < 4; j++) acc[i][j] = 0.f;

    const int la_r  = t & 63;
    const int la_k4 = (t >> 6) * 4;
    const int lb_k  = t >> 4;
    const int lb_c4 = (t & 15) * 4;

    const int k0 = ks * (Ddim / KS);

    for (int kt = k0; kt < k0 + Ddim / KS; kt += BK) {
        float4 a4 = *(const float4*)&A[(size_t)(rowBase + la_r) * Ddim + kt + la_k4];
        As[la_k4 + 0][la_r] = a4.x;
        As[la_k4 + 1][la_r] = a4.y;
        As[la_k4 + 2][la_r] = a4.z;
        As[la_k4 + 3][la_r] = a4.w;
        *(float4*)&Bs[lb_k][lb_c4] =
            *(const float4*)&W[(size_t)(kt + lb_k) * Ddim + colBase + lb_c4];
        __syncthreads();
#pragma unroll
        for (int kk = 0; kk < BK; kk++) {
            float ar[4], br[4];
            *(float4*)ar = *(const float4*)&As[kk][ty * 4];
            *(float4*)br = *(const float4*)&Bs[kk][tx * 4];
#pragma unroll
            for (int i = 0; i < 4; i++)
#pragma unroll
                for (int j = 0; j < 4; j++)
                    acc[i][j] += ar[i] * br[j];
        }
        __syncthreads();
    }

    float* P = g_proj_part + (size_t)(mslot * KS + ks) * ROWS * Ddim;
#pragma unroll
    for (int i = 0; i < 4; i++) {
        const int row = rowBase + ty * 4 + i;
        float4 v = make_float4(acc[i][0], acc[i][1], acc[i][2], acc[i][3]);
        *(float4*)&P[(size_t)row * Ddim + colBase + tx * 4] = v;
    }
}

// ---------------------------------------------------------------------------
// Combine split-K proj partials, add bias, scatter per mode.
// ---------------------------------------------------------------------------
__global__ void __launch_bounds__(256)
combine_proj(const float* __restrict__ bq, const float* __restrict__ bk,
             const float* __restrict__ bv, const float* __restrict__ bo,
             float* __restrict__ out,
             float* __restrict__ k_up, float* __restrict__ v_up,
             int mode_base)
{
    const int m   = mode_base ? 3 : (int)blockIdx.y;
    const int mslot = (m == 3) ? 0 : m;
    const int row = blockIdx.x;
    const int t   = threadIdx.x;
    const int col = t * 4;

    const float* bias = (m == 1) ? bk : (m == 2) ? bv : (m == 3) ? bo : bq;

    const float* P = g_proj_part + (size_t)(mslot * KS) * ROWS * Ddim
                   + (size_t)row * Ddim + col;
    float4 s = *(const float4*)&P[0];
#pragma unroll
    for (int ksl = 1; ksl < KS; ksl++) {
        float4 p = *(const float4*)&P[(size_t)ksl * ROWS * Ddim];
        s.x += p.x; s.y += p.y; s.z += p.z; s.w += p.w;
    }
    float4 bb = *(const float4*)&bias[col];
    s.x += bb.x; s.y += bb.y; s.z += bb.z; s.w += bb.w;

    const int b  = row >> 4;
    const int qi = row & 15;
    const int h  = col >> 6;
    const int dh = col & 63;

    if (m == 0) {
        *(float4*)&g_q_heads[(size_t)((b * Hdim + h) * Qdim + qi) * DH + dh] = s;
    } else if (m == 1) {
        *(float4*)&k_up[((size_t)(b * Hdim + h) * KLEN + Cdim + qi) * DH + dh] = s;
    } else if (m == 2) {
        *(float4*)&v_up[((size_t)(b * Hdim + h) * KLEN + Cdim + qi) * DH + dh] = s;
    } else {
        *(float4*)&out[(size_t)row * Ddim + col] = s;
    }
}

// ---------------------------------------------------------------------------
// Split-K fused attention + cache copy.  2048 blocks = (bh, split of 8).
// Scores computed from K registers (no Kt array); PV j-split with clean
// 128B LDS; packed f32x2 FMA throughout.
// ---------------------------------------------------------------------------
__global__ void __launch_bounds__(256)
attn_kernel(const float* __restrict__ cache_k, const float* __restrict__ cache_v,
            const int* __restrict__ mask,
            float* __restrict__ k_up, float* __restrict__ v_up)
{
    const int blk   = blockIdx.x;
    const int bh    = blk >> 3;
    const int split = blk & 7;
    const int b     = bh >> 4;

    __shared__ float Qst[16][68];    // [q][kk], pre-scaled by 1/8
    __shared__ float Vs[64][68];     // [j][dh]
    __shared__ float Ss[64][20];     // [j][q] scores -> probabilities
    __shared__ float s_corr[16];     // per-row correction factor per chunk
    __shared__ float s_red[128][8];  // PV js-combine scratch

    const int t = threadIdx.x;

    for (int i = t; i < Qdim * DH; i += 256) {
        const int q  = i >> 6;
        const int kk = i & 63;
        Qst[q][kk] = g_q_heads[(size_t)(bh * Qdim + q) * DH + kk] * 0.125f;
    }

    const int lj = t >> 2;           // 0..63 : KV row owned for load/scores
    const int g  = t & 3;            // k-slice (interleaved: kk = g*4 + 16e)

    const int row    = t >> 4;       // softmax role
    const int lane16 = t & 15;

    const int js  = t >> 7;          // PV role: j parity
    const int rr  = (t >> 3) & 15;   // PV row
    const int dhg = t & 7;           // PV dh-group (dh = dhg*4.. and 32+dhg*4..)

    float m_i = -1e30f, l_i = 0.f;
    unsigned long long a0 = 0ull, a1 = 0ull, a2 = 0ull, a3 = 0ull;

    const float* Kb = cache_k + (size_t)bh * Cdim * DH;
    const float* Vb = cache_v + (size_t)bh * Cdim * DH;
    float* Kout = k_up + (size_t)bh * KLEN * DH;
    float* Vout = v_up + (size_t)bh * KLEN * DH;
    const int* Mb = mask + (size_t)b * Qdim * KLEN;

    float4 kf[4], vf[4];

    auto prefetch_kv = [&](int c) {
        if (c < 64) {
#pragma unroll
            for (int e = 0; e < 4; e++) {
                const size_t off = ((size_t)(c * 64 + lj)) * DH + g * 4 + e * 16;
                kf[e] = *(const float4*)&Kb[off];
                vf[e] = *(const float4*)&Vb[off];
            }
        } else if (lj < 16) {
#pragma unroll
            for (int e = 0; e < 4; e++) {
                const size_t off = ((size_t)(Cdim + lj)) * DH + g * 4 + e * 16;
                kf[e] = *(const float4*)&Kout[off];
                vf[e] = *(const float4*)&Vout[off];
            }
        }
    };

    prefetch_kv(split);

    for (int c = split; c < 65; c += NSPLIT) {
        const int kvBase = c * 64;
        const bool full  = (c < 64);

        __syncthreads();   // prev PV done with Vs/Ss (and Qst ready on iter 0)

        // --- commit V to smem, fused K/V cache copy to gmem ---
        if (full) {
#pragma unroll
            for (int e = 0; e < 4; e++) {
                const int kk = g * 4 + e * 16;
                const size_t off = ((size_t)(kvBase + lj)) * DH + kk;
                *(float4*)&Kout[off] = kf[e];
                *(float4*)&Vout[off] = vf[e];
                *(float4*)&Vs[lj][kk] = vf[e];
            }
        } else if (lj < 16) {
#pragma unroll
            for (int e = 0; e < 4; e++) {
                const int kk = g * 4 + e * 16;
                *(float4*)&Vs[lj][kk] = vf[e];
            }
        }

        // --- scores from K registers: partials for all 16 q over 16 kk ---
        {
            float s[16];
#pragma unroll
            for (int q = 0; q < 16; q++) s[q] = 0.f;
#pragma unroll
            for (int e = 0; e < 4; e++) {
                const float4 kv = kf[e];
#pragma unroll
                for (int q = 0; q < 16; q++) {
                    float4 qv = *(const float4*)&Qst[q][g * 4 + e * 16];
                    s[q] += qv.x * kv.x + qv.y * kv.y + qv.z * kv.z + qv.w * kv.w;
                }
            }
            // butterfly reduce across the 4 k-slice lanes (bits 0-1 of t)
#pragma unroll
            for (int mk = 1; mk <= 2; mk <<= 1)
#pragma unroll
                for (int q = 0; q < 16; q++)
                    s[q] += __shfl_xor_sync(0xffffffffu, s[q], mk);
            // lane g stores its quad Ss[lj][4g..4g+3]
            float4 v;
            if      (g == 0) v = make_float4(s[0],  s[1],  s[2],  s[3]);
            else if (g == 1) v = make_float4(s[4],  s[5],  s[6],  s[7]);
            else if (g == 2) v = make_float4(s[8],  s[9],  s[10], s[11]);
            else             v = make_float4(s[12], s[13], s[14], s[15]);
            *(float4*)&Ss[lj][g * 4] = v;
        }

        // mask for this chunk (row-owner registers)
        int mcur[4];
        const int cb = full ? 64 : 16;
#pragma unroll
        for (int e = 0; e < 4; e++) {
            const int j = lane16 + e * 16;
            mcur[e] = (j < cb) ? Mb[row * KLEN + kvBase + j] : 0;
        }

        // prefetch next chunk (long latency hidden behind softmax + PV)
        if (c + NSPLIT < 65) prefetch_kv(c + NSPLIT);

        __syncthreads();

        // --- online softmax: 16 threads per query row ---
        {
            float sv[4];
            float mx = -1e30f;
#pragma unroll
            for (int e = 0; e < 4; e++) {
                float s = Ss[lane16 + e * 16][row];
                if (mcur[e] == 0) s = -1e9f;
                sv[e] = s;
                mx = fmaxf(mx, s);
            }
#pragma unroll
            for (int off = 8; off; off >>= 1)
                mx = fmaxf(mx, __shfl_xor_sync(0xffffffffu, mx, off));
            const float m_new = fmaxf(m_i, mx);
            const float corr  = __expf(m_i - m_new);
            float lsum = 0.f;
#pragma unroll
            for (int e = 0; e < 4; e++) {
                const float p = __expf(sv[e] - m_new);
                Ss[lane16 + e * 16][row] = p;
                lsum += p;
            }
#pragma unroll
            for (int off = 8; off; off >>= 1)
                lsum += __shfl_xor_sync(0xffffffffu, lsum, off);
            l_i = l_i * corr + lsum;
            m_i = m_new;
            if (lane16 == 0) s_corr[row] = corr;
        }
        __syncthreads();

        // --- PV: thread = (js, rr, dhg); j = js, js+2, ..., packed FFMA2 ---
        {
            const float corr_v = s_corr[rr];
            unsigned long long corr2;
            asm("mov.b64 %0, {%1, %1};" : "=l"(corr2) : "f"(corr_v));
            asm("mul.rn.f32x2 %0, %0, %1;" : "+l"(a0) : "l"(corr2));
            asm("mul.rn.f32x2 %0, %0, %1;" : "+l"(a1) : "l"(corr2));
            asm("mul.rn.f32x2 %0, %0, %1;" : "+l"(a2) : "l"(corr2));
            asm("mul.rn.f32x2 %0, %0, %1;" : "+l"(a3) : "l"(corr2));
#pragma unroll 8
            for (int j = js; j < 64; j += 2) {
                const float p = Ss[j][rr];
                unsigned long long p2;
                asm("mov.b64 %0, {%1, %1};" : "=l"(p2) : "f"(p));
                ulonglong2 v0 = *reinterpret_cast<const ulonglong2*>(&Vs[j][dhg * 4]);
                ulonglong2 v1 = *reinterpret_cast<const ulonglong2*>(&Vs[j][32 + dhg * 4]);
                asm("fma.rn.f32x2 %0, %1, %2, %0;" : "+l"(a0) : "l"(v0.x), "l"(p2));
                asm("fma.rn.f32x2 %0, %1, %2, %0;" : "+l"(a1) : "l"(v0.y), "l"(p2));
                asm("fma.rn.f32x2 %0, %1, %2, %0;" : "+l"(a2) : "l"(v1.x), "l"(p2));
                asm("fma.rn.f32x2 %0, %1, %2, %0;" : "+l"(a3) : "l"(v1.y), "l"(p2));
            }
        }
    }

    // (m, l) partials
    if (lane16 == 0)
        g_part_ml[(bh * NSPLIT + split) * Qdim + row] = make_float2(m_i, l_i);

    // js-combine and store unnormalized acc partials
    float f0, f1, f2, f3, f4, f5, f6, f7;
    asm("mov.b64 {%0, %1}, %2;" : "=f"(f0), "=f"(f1) : "l"(a0));
    asm("mov.b64 {%0, %1}, %2;" : "=f"(f2), "=f"(f3) : "l"(a1));
    asm("mov.b64 {%0, %1}, %2;" : "=f"(f4), "=f"(f5) : "l"(a2));
    asm("mov.b64 {%0, %1}, %2;" : "=f"(f6), "=f"(f7) : "l"(a3));

    if (js == 1) {
        float* r = s_red[t - 128];
        r[0] = f0; r[1] = f1; r[2] = f2; r[3] = f3;
        r[4] = f4; r[5] = f5; r[6] = f6; r[7] = f7;
    }
    __syncthreads();
    if (js == 0) {
        const float* r = s_red[t];
        const size_t base = ((size_t)(bh * NSPLIT + split) * Qdim + rr) * DH;
        float4 o0 = make_float4(f0 + r[0], f1 + r[1], f2 + r[2], f3 + r[3]);
        float4 o1 = make_float4(f4 + r[4], f5 + r[5], f6 + r[6], f7 + r[7]);
        *(float4*)&g_part_acc[base + dhg * 4]      = o0;
        *(float4*)&g_part_acc[base + 32 + dhg * 4] = o1;
    }
}

// ---------------------------------------------------------------------------
// Combine attention split partials -> g_attn_x
// ---------------------------------------------------------------------------
__global__ void __launch_bounds__(256)
combine_kernel()
{
    const int bh  = blockIdx.x;
    const int t   = threadIdx.x;
    const int row = t >> 4;
    const int dh0 = (t & 15) * 4;

    float2 ml[NSPLIT];
    float m = -1e30f;
#pragma unroll
    for (int s = 0; s < NSPLIT; s++) {
        ml[s] = g_part_ml[(bh * NSPLIT + s) * Qdim + row];
        m = fmaxf(m, ml[s].x);
    }
    float l = 0.f;
    float4 o = make_float4(0.f, 0.f, 0.f, 0.f);
#pragma unroll
    for (int s = 0; s < NSPLIT; s++) {
        const float w = __expf(ml[s].x - m);
        l += ml[s].y * w;
        float4 a = *(const float4*)&g_part_acc[((size_t)(bh * NSPLIT + s) * Qdim + row) * DH + dh0];
        o.x += a.x * w; o.y += a.y * w; o.z += a.z * w; o.w += a.w * w;
    }
    const float inv = 1.f / l;
    const int b = bh >> 4;
    const int h = bh & 15;
    o.x *= inv; o.y *= inv; o.z *= inv; o.w *= inv;
    *(float4*)&g_attn_x[(size_t)(b * Qdim + row) * Ddim + h * DH + dh0] = o;
}

// ---------------------------------------------------------------------------
extern "C" void kernel_launch(void* const* d_in, const int* in_sizes, int n_in,
                              void* d_out, int out_size)
{
    const float* query   = (const float*)d_in[0];
    const float* key     = (const float*)d_in[1];
    const float* value   = (const float*)d_in[2];
    const int*   mask    = (const int*)d_in[3];
    const float* cache_k = (const float*)d_in[4];
    const float* cache_v = (const float*)d_in[5];
    const float* Wq = (const float*)d_in[6];
    const float* bq = (const float*)d_in[7];
    const float* Wk = (const float*)d_in[8];
    const float* bk = (const float*)d_in[9];
    const float* Wv = (const float*)d_in[10];
    const float* bv = (const float*)d_in[11];
    const float* Wo = (const float*)d_in[12];
    const float* bo = (const float*)d_in[13];

    float* out  = (float*)d_out;
    float* k_up = out + (size_t)Bdim * Qdim * Ddim;
    float* v_up = k_up + (size_t)Bdim * Hdim * KLEN * DH;

    proj_kernel<<<dim3(4, 16, 3 * KS), 256>>>(query, key, value,
                                              Wq, Wk, Wv, 0);
    combine_proj<<<dim3(ROWS, 3), 256>>>(bq, bk, bv, bo, out, k_up, v_up, 0);

    attn_kernel<<<Bdim * Hdim * NSPLIT, 256>>>(cache_k, cache_v, mask, k_up, v_up);

    combine_kernel<<<Bdim * Hdim, 256>>>();

    proj_kernel<<<dim3(4, 16, KS), 256>>>(nullptr, nullptr, nullptr,
                                          Wo, nullptr, nullptr, 1);
    combine_proj<<<dim3(ROWS, 1), 256>>>(bq, bk, bv, bo, out, k_up, v_up, 1);
}

// round 7
// speedup vs baseline: 1.4481x; 1.0108x over previous
#include <cuda_runtime.h>
#include <cstddef>
#include <cstdint>

// ---------------------------------------------------------------------------
// MultiHeadedAttentionWithCache  (B=16,Q=16,D=1024,H=16,DH=64,C=4096,KLEN=4112)
// d_out = concat(out[16,16,1024], k_up[16,16,4112,64], v_up[16,16,4112,64])
// ---------------------------------------------------------------------------

#define Bdim 16
#define Qdim 16
#define Ddim 1024
#define Hdim 16
#define DH   64
#define Cdim 4096
#define KLEN 4112
#define ROWS 256
#define NSPLIT 8
#define KS 4

__device__ float  g_q_heads[ROWS * Ddim];
__device__ float  g_attn_x[ROWS * Ddim];
__device__ float  g_part_acc[256 * NSPLIT * Qdim * DH];
__device__ float2 g_part_ml[256 * NSPLIT * Qdim];
__device__ float  g_proj_part[3 * KS * ROWS * Ddim];

// ---------------------------------------------------------------------------
// Projection GEMM, split-K
// ---------------------------------------------------------------------------
#define BM 64
#define BN 64
#define BK 16

__global__ void __launch_bounds__(256)
proj_kernel(const float* __restrict__ Aq, const float* __restrict__ Ak,
            const float* __restrict__ Av,
            const float* __restrict__ Wq, const float* __restrict__ Wk,
            const float* __restrict__ Wv,
            int mode_base)
{
    const int zz = blockIdx.z;
    const int m  = mode_base ? 3 : (zz / KS);
    const int ks = mode_base ? zz : (zz % KS);
    const int mslot = (m == 3) ? 0 : m;

    const float* A = (m == 0) ? Aq : (m == 1) ? Ak : (m == 2) ? Av : g_attn_x;
    const float* W = (m == 1) ? Wk : (m == 2) ? Wv : Wq;

    __shared__ float As[BK][BM + 4];
    __shared__ float Bs[BK][BN];

    const int rowBase = blockIdx.x * BM;
    const int colBase = blockIdx.y * BN;

    const int t  = threadIdx.x;
    const int tx = t & 15;
    const int ty = t >> 4;

    float acc[4][4];
#pragma unroll
    for (int i = 0; i < 4; i++)
#pragma unroll
        for (int j = 0; j < 4; j++) acc[i][j] = 0.f;

    const int la_r  = t & 63;
    const int la_k4 = (t >> 6) * 4;
    const int lb_k  = t >> 4;
    const int lb_c4 = (t & 15) * 4;

    const int k0 = ks * (Ddim / KS);

    for (int kt = k0; kt < k0 + Ddim / KS; kt += BK) {
        float4 a4 = *(const float4*)&A[(size_t)(rowBase + la_r) * Ddim + kt + la_k4];
        As[la_k4 + 0][la_r] = a4.x;
        As[la_k4 + 1][la_r] = a4.y;
        As[la_k4 + 2][la_r] = a4.z;
        As[la_k4 + 3][la_r] = a4.w;
        *(float4*)&Bs[lb_k][lb_c4] =
            *(const float4*)&W[(size_t)(kt + lb_k) * Ddim + colBase + lb_c4];
        __syncthreads();
#pragma unroll
        for (int kk = 0; kk < BK; kk++) {
            float ar[4], br[4];
            *(float4*)ar = *(const float4*)&As[kk][ty * 4];
            *(float4*)br = *(const float4*)&Bs[kk][tx * 4];
#pragma unroll
            for (int i = 0; i < 4; i++)
#pragma unroll
                for (int j = 0; j < 4; j++)
                    acc[i][j] += ar[i] * br[j];
        }
        __syncthreads();
    }

    float* P = g_proj_part + (size_t)(mslot * KS + ks) * ROWS * Ddim;
#pragma unroll
    for (int i = 0; i < 4; i++) {
        const int row = rowBase + ty * 4 + i;
        float4 v = make_float4(acc[i][0], acc[i][1], acc[i][2], acc[i][3]);
        *(float4*)&P[(size_t)row * Ddim + colBase + tx * 4] = v;
    }
}

// ---------------------------------------------------------------------------
// Combine split-K proj partials + bias + scatter (one mode per launch)
// ---------------------------------------------------------------------------
__global__ void __launch_bounds__(256)
combine_proj(const float* __restrict__ bias_in,
             float* __restrict__ out,
             float* __restrict__ k_up, float* __restrict__ v_up,
             int m)
{
    const int mslot = (m == 3) ? 0 : m;
    const int row = blockIdx.x;
    const int t   = threadIdx.x;
    const int col = t * 4;

    const float* P = g_proj_part + (size_t)(mslot * KS) * ROWS * Ddim
                   + (size_t)row * Ddim + col;
    float4 s = *(const float4*)&P[0];
#pragma unroll
    for (int ksl = 1; ksl < KS; ksl++) {
        float4 p = *(const float4*)&P[(size_t)ksl * ROWS * Ddim];
        s.x += p.x; s.y += p.y; s.z += p.z; s.w += p.w;
    }
    float4 bb = *(const float4*)&bias_in[col];
    s.x += bb.x; s.y += bb.y; s.z += bb.z; s.w += bb.w;

    const int b  = row >> 4;
    const int qi = row & 15;
    const int h  = col >> 6;
    const int dh = col & 63;

    if (m == 0) {
        *(float4*)&g_q_heads[(size_t)((b * Hdim + h) * Qdim + qi) * DH + dh] = s;
    } else if (m == 1) {
        *(float4*)&k_up[((size_t)(b * Hdim + h) * KLEN + Cdim + qi) * DH + dh] = s;
    } else if (m == 2) {
        *(float4*)&v_up[((size_t)(b * Hdim + h) * KLEN + Cdim + qi) * DH + dh] = s;
    } else {
        *(float4*)&out[(size_t)row * Ddim + col] = s;
    }
}

// ---------------------------------------------------------------------------
// cp.async helpers
// ---------------------------------------------------------------------------
__device__ __forceinline__ void cp_async16(unsigned int smem_addr, const void* gptr) {
    asm volatile("cp.async.cg.shared.global [%0], [%1], 16;\n"
                 :: "r"(smem_addr), "l"(gptr) : "memory");
}
__device__ __forceinline__ void cp_commit() {
    asm volatile("cp.async.commit_group;\n" ::: "memory");
}
__device__ __forceinline__ void cp_wait1() {
    asm volatile("cp.async.wait_group 1;\n" ::: "memory");
}

// ---------------------------------------------------------------------------
// Split-K fused attention + cache copy.
// K: LDG->regs (scores from registers, STG copy at commit).
// V: cp.async double-buffered smem; STG copy fused into PV (rr==0 lanes).
// 4 blocks/SM via __launch_bounds__(256,4).
// ---------------------------------------------------------------------------
__global__ void __launch_bounds__(256, 4)
attn_kernel(const float* __restrict__ cache_k, const float* __restrict__ cache_v,
            const int* __restrict__ mask,
            float* __restrict__ k_up, float* __restrict__ v_up)
{
    const int blk   = blockIdx.x;
    const int bh    = blk >> 3;
    const int split = blk & 7;
    const int b     = bh >> 4;

    __shared__ float Qst[16][68];      // [q][kk], pre-scaled by 1/8
    __shared__ float Vs[2][64][68];    // double-buffered V chunk
    __shared__ float Ss[64][20];       // [j][q]
    __shared__ float s_corr[16];
    __shared__ float s_red[128][8];

    const int t = threadIdx.x;

    for (int i = t; i < Qdim * DH; i += 256) {
        const int q  = i >> 6;
        const int kk = i & 63;
        Qst[q][kk] = g_q_heads[(size_t)(bh * Qdim + q) * DH + kk] * 0.125f;
    }

    const int lj = t >> 2;           // 0..63 KV row for load/scores
    const int g  = t & 3;            // k-slice: kk = g*4 + e*16

    const int row    = t >> 4;       // softmax role
    const int lane16 = t & 15;

    const int js  = t >> 7;          // PV: j parity
    const int rr  = (t >> 3) & 15;   // PV: row
    const int dhg = t & 7;           // PV: dh-group

    float m_i = -1e30f, l_i = 0.f;
    unsigned long long a0 = 0ull, a1 = 0ull, a2 = 0ull, a3 = 0ull;

    const float* Kb = cache_k + (size_t)bh * Cdim * DH;
    const float* Vb = cache_v + (size_t)bh * Cdim * DH;
    float* Kout = k_up + (size_t)bh * KLEN * DH;
    float* Vout = v_up + (size_t)bh * KLEN * DH;
    const int* Mb = mask + (size_t)b * Qdim * KLEN;

    float4 kf[4];
    int cur = 0;

    auto prefetch_k = [&](int c) {
        if (c < 64) {
#pragma unroll
            for (int e = 0; e < 4; e++)
                kf[e] = *(const float4*)&Kb[((size_t)(c * 64 + lj)) * DH + g * 4 + e * 16];
        } else if (lj < 16) {
#pragma unroll
            for (int e = 0; e < 4; e++)
                kf[e] = *(const float4*)&Kout[((size_t)(Cdim + lj)) * DH + g * 4 + e * 16];
        }
    };

    // issue V cp.async for chunk c into buffer buf (always commits a group)
    auto issue_v = [&](int c, int buf) {
        if (c < 64) {
#pragma unroll
            for (int e = 0; e < 4; e++) {
                const int kk = g * 4 + e * 16;
                unsigned int sa = (unsigned int)__cvta_generic_to_shared(&Vs[buf][lj][kk]);
                cp_async16(sa, &Vb[((size_t)(c * 64 + lj)) * DH + kk]);
            }
        } else if (c == 64) {
            if (lj < 16) {
#pragma unroll
                for (int e = 0; e < 4; e++) {
                    const int kk = g * 4 + e * 16;
                    unsigned int sa = (unsigned int)__cvta_generic_to_shared(&Vs[buf][lj][kk]);
                    cp_async16(sa, &Vout[((size_t)(Cdim + lj)) * DH + kk]);
                }
            } else {
#pragma unroll
                for (int e = 0; e < 4; e++)
                    *(float4*)&Vs[buf][lj][g * 4 + e * 16] = make_float4(0.f, 0.f, 0.f, 0.f);
            }
        }
        cp_commit();
    };

    prefetch_k(split);
    issue_v(split, 0);

    for (int c = split; c < 65; c += NSPLIT) {
        const int kvBase = c * 64;
        const bool full  = (c < 64);

        __syncthreads();   // prev PV done (frees Vs[nxt] for cp.async), Qst ready

        // K cache copy (from registers)
        if (full) {
#pragma unroll
            for (int e = 0; e < 4; e++)
                *(float4*)&Kout[((size_t)(kvBase + lj)) * DH + g * 4 + e * 16] = kf[e];
        }

        // start V load for the next chunk into the other buffer
        issue_v(c + NSPLIT, cur ^ 1);

        // --- scores from K registers: 2 passes of 8 queries ---
#pragma unroll
        for (int p = 0; p < 2; p++) {
            float s[8];
#pragma unroll
            for (int q = 0; q < 8; q++) s[q] = 0.f;
#pragma unroll
            for (int e = 0; e < 4; e++) {
                const float4 kv = kf[e];
#pragma unroll
                for (int q = 0; q < 8; q++) {
                    float4 qv = *(const float4*)&Qst[p * 8 + q][g * 4 + e * 16];
                    s[q] += qv.x * kv.x + qv.y * kv.y + qv.z * kv.z + qv.w * kv.w;
                }
            }
#pragma unroll
            for (int mk = 1; mk <= 2; mk <<= 1)
#pragma unroll
                for (int q = 0; q < 8; q++)
                    s[q] += __shfl_xor_sync(0xffffffffu, s[q], mk);
            // lane g stores queries p*8 + 2g, 2g+1
            *(float2*)&Ss[lj][p * 8 + g * 2] = make_float2(s[g * 2], s[g * 2 + 1]);
        }

        // mask for this chunk
        int mcur[4];
        const int cb = full ? 64 : 16;
#pragma unroll
        for (int e = 0; e < 4; e++) {
            const int j = lane16 + e * 16;
            mcur[e] = (j < cb) ? Mb[row * KLEN + kvBase + j] : 0;
        }

        // K prefetch for next chunk
        if (c + NSPLIT < 65) prefetch_k(c + NSPLIT);

        __syncthreads();   // Ss ready

        // --- online softmax ---
        {
            float sv[4];
            float mx = -1e30f;
#pragma unroll
            for (int e = 0; e < 4; e++) {
                float s = Ss[lane16 + e * 16][row];
                if (mcur[e] == 0) s = -1e9f;
                sv[e] = s;
                mx = fmaxf(mx, s);
            }
#pragma unroll
            for (int off = 8; off; off >>= 1)
                mx = fmaxf(mx, __shfl_xor_sync(0xffffffffu, mx, off));
            const float m_new = fmaxf(m_i, mx);
            const float corr  = __expf(m_i - m_new);
            float lsum = 0.f;
#pragma unroll
            for (int e = 0; e < 4; e++) {
                const float p = __expf(sv[e] - m_new);
                Ss[lane16 + e * 16][row] = p;
                lsum += p;
            }
#pragma unroll
            for (int off = 8; off; off >>= 1)
                lsum += __shfl_xor_sync(0xffffffffu, lsum, off);
            l_i = l_i * corr + lsum;
            m_i = m_new;
            if (lane16 == 0) s_corr[row] = corr;
        }

        cp_wait1();        // current chunk's V resident
        __syncthreads();   // probs + corr + Vs[cur] visible

        // --- PV (+ fused V cache copy from rr==0 lanes) ---
        {
            const float corr_v = s_corr[rr];
            unsigned long long corr2;
            asm("mov.b64 %0, {%1, %1};" : "=l"(corr2) : "f"(corr_v));
            asm("mul.rn.f32x2 %0, %0, %1;" : "+l"(a0) : "l"(corr2));
            asm("mul.rn.f32x2 %0, %0, %1;" : "+l"(a1) : "l"(corr2));
            asm("mul.rn.f32x2 %0, %0, %1;" : "+l"(a2) : "l"(corr2));
            asm("mul.rn.f32x2 %0, %0, %1;" : "+l"(a3) : "l"(corr2));
            const bool doCopy = full && (rr == 0);
#pragma unroll 8
            for (int j = js; j < 64; j += 2) {
                const float p = Ss[j][rr];
                unsigned long long p2;
                asm("mov.b64 %0, {%1, %1};" : "=l"(p2) : "f"(p));
                ulonglong2 v0 = *reinterpret_cast<const ulonglong2*>(&Vs[cur][j][dhg * 4]);
                ulonglong2 v1 = *reinterpret_cast<const ulonglong2*>(&Vs[cur][j][32 + dhg * 4]);
                if (doCopy) {
                    float* dst = &Vout[((size_t)(kvBase + j)) * DH];
                    *(ulonglong2*)&dst[dhg * 4]      = v0;
                    *(ulonglong2*)&dst[32 + dhg * 4] = v1;
                }
                asm("fma.rn.f32x2 %0, %1, %2, %0;" : "+l"(a0) : "l"(v0.x), "l"(p2));
                asm("fma.rn.f32x2 %0, %1, %2, %0;" : "+l"(a1) : "l"(v0.y), "l"(p2));
                asm("fma.rn.f32x2 %0, %1, %2, %0;" : "+l"(a2) : "l"(v1.x), "l"(p2));
                asm("fma.rn.f32x2 %0, %1, %2, %0;" : "+l"(a3) : "l"(v1.y), "l"(p2));
            }
        }
        cur ^= 1;
    }

    if (lane16 == 0)
        g_part_ml[(bh * NSPLIT + split) * Qdim + row] = make_float2(m_i, l_i);

    float f0, f1, f2, f3, f4, f5, f6, f7;
    asm("mov.b64 {%0, %1}, %2;" : "=f"(f0), "=f"(f1) : "l"(a0));
    asm("mov.b64 {%0, %1}, %2;" : "=f"(f2), "=f"(f3) : "l"(a1));
    asm("mov.b64 {%0, %1}, %2;" : "=f"(f4), "=f"(f5) : "l"(a2));
    asm("mov.b64 {%0, %1}, %2;" : "=f"(f6), "=f"(f7) : "l"(a3));

    if (js == 1) {
        float* r = s_red[t - 128];
        r[0] = f0; r[1] = f1; r[2] = f2; r[3] = f3;
        r[4] = f4; r[5] = f5; r[6] = f6; r[7] = f7;
    }
    __syncthreads();
    if (js == 0) {
        const float* r = s_red[t];
        const size_t base = ((size_t)(bh * NSPLIT + split) * Qdim + rr) * DH;
        float4 o0 = make_float4(f0 + r[0], f1 + r[1], f2 + r[2], f3 + r[3]);
        float4 o1 = make_float4(f4 + r[4], f5 + r[5], f6 + r[6], f7 + r[7]);
        *(float4*)&g_part_acc[base + dhg * 4]      = o0;
        *(float4*)&g_part_acc[base + 32 + dhg * 4] = o1;
    }
}

// ---------------------------------------------------------------------------
// Combine attention split partials -> g_attn_x
// ---------------------------------------------------------------------------
__global__ void __launch_bounds__(256)
combine_kernel()
{
    const int bh  = blockIdx.x;
    const int t   = threadIdx.x;
    const int row = t >> 4;
    const int dh0 = (t & 15) * 4;

    float2 ml[NSPLIT];
    float m = -1e30f;
#pragma unroll
    for (int s = 0; s < NSPLIT; s++) {
        ml[s] = g_part_ml[(bh * NSPLIT + s) * Qdim + row];
        m = fmaxf(m, ml[s].x);
    }
    float l = 0.f;
    float4 o = make_float4(0.f, 0.f, 0.f, 0.f);
#pragma unroll
    for (int s = 0; s < NSPLIT; s++) {
        const float w = __expf(ml[s].x - m);
        l += ml[s].y * w;
        float4 a = *(const float4*)&g_part_acc[((size_t)(bh * NSPLIT + s) * Qdim + row) * DH + dh0];
        o.x += a.x * w; o.y += a.y * w; o.z += a.z * w; o.w += a.w * w;
    }
    const float inv = 1.f / l;
    const int b = bh >> 4;
    const int h = bh & 15;
    o.x *= inv; o.y *= inv; o.z *= inv; o.w *= inv;
    *(float4*)&g_attn_x[(size_t)(b * Qdim + row) * Ddim + h * DH + dh0] = o;
}

// ---------------------------------------------------------------------------
extern "C" void kernel_launch(void* const* d_in, const int* in_sizes, int n_in,
                              void* d_out, int out_size)
{
    const float* query   = (const float*)d_in[0];
    const float* key     = (const float*)d_in[1];
    const float* value   = (const float*)d_in[2];
    const int*   mask    = (const int*)d_in[3];
    const float* cache_k = (const float*)d_in[4];
    const float* cache_v = (const float*)d_in[5];
    const float* Wq = (const float*)d_in[6];
    const float* bq = (const float*)d_in[7];
    const float* Wk = (const float*)d_in[8];
    const float* bk = (const float*)d_in[9];
    const float* Wv = (const float*)d_in[10];
    const float* bv = (const float*)d_in[11];
    const float* Wo = (const float*)d_in[12];
    const float* bo = (const float*)d_in[13];

    float* out  = (float*)d_out;
    float* k_up = out + (size_t)Bdim * Qdim * Ddim;
    float* v_up = k_up + (size_t)Bdim * Hdim * KLEN * DH;

    // launches 1-4 (so attn_kernel is the 5th launch for ncu -s 5)
    proj_kernel<<<dim3(4, 16, 3 * KS), 256>>>(query, key, value, Wq, Wk, Wv, 0);
    combine_proj<<<ROWS, 256>>>(bq, out, k_up, v_up, 0);
    combine_proj<<<ROWS, 256>>>(bk, out, k_up, v_up, 1);
    combine_proj<<<ROWS, 256>>>(bv, out, k_up, v_up, 2);

    // 5: attention
    attn_kernel<<<Bdim * Hdim * NSPLIT, 256>>>(cache_k, cache_v, mask, k_up, v_up);

    combine_kernel<<<Bdim * Hdim, 256>>>();

    proj_kernel<<<dim3(4, 16, KS), 256>>>(nullptr, nullptr, nullptr, Wo, nullptr, nullptr, 1);
    combine_proj<<<ROWS, 256>>>(bo, out, k_up, v_up, 3);
}

// round 8
// speedup vs baseline: 1.4602x; 1.0083x over previous
#include <cuda_runtime.h>
#include <cstddef>
#include <cstdint>

// ---------------------------------------------------------------------------
// MultiHeadedAttentionWithCache  (B=16,Q=16,D=1024,H=16,DH=64,C=4096,KLEN=4112)
// d_out = concat(out[16,16,1024], k_up[16,16,4112,64], v_up[16,16,4112,64])
// ---------------------------------------------------------------------------

#define Bdim 16
#define Qdim 16
#define Ddim 1024
#define Hdim 16
#define DH   64
#define Cdim 4096
#define KLEN 4112
#define ROWS 256
#define NSPLIT 8
#define KS 4

__device__ float  g_q_heads[ROWS * Ddim];
__device__ float  g_attn_x[ROWS * Ddim];
__device__ float  g_part_acc[256 * NSPLIT * Qdim * DH];
__device__ float2 g_part_ml[256 * NSPLIT * Qdim];
__device__ float  g_proj_part[3 * KS * ROWS * Ddim];

// ---------------------------------------------------------------------------
// Projection GEMM, split-K
// ---------------------------------------------------------------------------
#define BM 64
#define BN 64
#define BK 16

__global__ void __launch_bounds__(256)
proj_kernel(const float* __restrict__ Aq, const float* __restrict__ Ak,
            const float* __restrict__ Av,
            const float* __restrict__ Wq, const float* __restrict__ Wk,
            const float* __restrict__ Wv,
            int mode_base)
{
    const int zz = blockIdx.z;
    const int m  = mode_base ? 3 : (zz / KS);
    const int ks = mode_base ? zz : (zz % KS);
    const int mslot = (m == 3) ? 0 : m;

    const float* A = (m == 0) ? Aq : (m == 1) ? Ak : (m == 2) ? Av : g_attn_x;
    const float* W = (m == 1) ? Wk : (m == 2) ? Wv : Wq;

    __shared__ float As[BK][BM + 4];
    __shared__ float Bs[BK][BN];

    const int rowBase = blockIdx.x * BM;
    const int colBase = blockIdx.y * BN;

    const int t  = threadIdx.x;
    const int tx = t & 15;
    const int ty = t >> 4;

    float acc[4][4];
#pragma unroll
    for (int i = 0; i < 4; i++)
#pragma unroll
        for (int j = 0; j < 4; j++) acc[i][j] = 0.f;

    const int la_r  = t & 63;
    const int la_k4 = (t >> 6) * 4;
    const int lb_k  = t >> 4;
    const int lb_c4 = (t & 15) * 4;

    const int k0 = ks * (Ddim / KS);

    for (int kt = k0; kt < k0 + Ddim / KS; kt += BK) {
        float4 a4 = *(const float4*)&A[(size_t)(rowBase + la_r) * Ddim + kt + la_k4];
        As[la_k4 + 0][la_r] = a4.x;
        As[la_k4 + 1][la_r] = a4.y;
        As[la_k4 + 2][la_r] = a4.z;
        As[la_k4 + 3][la_r] = a4.w;
        *(float4*)&Bs[lb_k][lb_c4] =
            *(const float4*)&W[(size_t)(kt + lb_k) * Ddim + colBase + lb_c4];
        __syncthreads();
#pragma unroll
        for (int kk = 0; kk < BK; kk++) {
            float ar[4], br[4];
            *(float4*)ar = *(const float4*)&As[kk][ty * 4];
            *(float4*)br = *(const float4*)&Bs[kk][tx * 4];
#pragma unroll
            for (int i = 0; i < 4; i++)
#pragma unroll
                for (int j = 0; j < 4; j++)
                    acc[i][j] += ar[i] * br[j];
        }
        __syncthreads();
    }

    float* P = g_proj_part + (size_t)(mslot * KS + ks) * ROWS * Ddim;
#pragma unroll
    for (int i = 0; i < 4; i++) {
        const int row = rowBase + ty * 4 + i;
        float4 v = make_float4(acc[i][0], acc[i][1], acc[i][2], acc[i][3]);
        *(float4*)&P[(size_t)row * Ddim + colBase + tx * 4] = v;
    }
}

// ---------------------------------------------------------------------------
// Combine split-K proj partials + bias + scatter
// ---------------------------------------------------------------------------
__device__ __forceinline__ void combine_proj_body(
    const float* __restrict__ bias_in,
    float* __restrict__ out,
    float* __restrict__ k_up, float* __restrict__ v_up,
    int m, int row, int t)
{
    const int mslot = (m == 3) ? 0 : m;
    const int col = t * 4;

    const float* P = g_proj_part + (size_t)(mslot * KS) * ROWS * Ddim
                   + (size_t)row * Ddim + col;
    float4 s = *(const float4*)&P[0];
#pragma unroll
    for (int ksl = 1; ksl < KS; ksl++) {
        float4 p = *(const float4*)&P[(size_t)ksl * ROWS * Ddim];
        s.x += p.x; s.y += p.y; s.z += p.z; s.w += p.w;
    }
    float4 bb = *(const float4*)&bias_in[col];
    s.x += bb.x; s.y += bb.y; s.z += bb.z; s.w += bb.w;

    const int b  = row >> 4;
    const int qi = row & 15;
    const int h  = col >> 6;
    const int dh = col & 63;

    if (m == 0) {
        *(float4*)&g_q_heads[(size_t)((b * Hdim + h) * Qdim + qi) * DH + dh] = s;
    } else if (m == 1) {
        *(float4*)&k_up[((size_t)(b * Hdim + h) * KLEN + Cdim + qi) * DH + dh] = s;
    } else if (m == 2) {
        *(float4*)&v_up[((size_t)(b * Hdim + h) * KLEN + Cdim + qi) * DH + dh] = s;
    } else {
        *(float4*)&out[(size_t)row * Ddim + col] = s;
    }
}

__global__ void __launch_bounds__(256)
combine_proj(const float* __restrict__ bias_in,
             float* __restrict__ out,
             float* __restrict__ k_up, float* __restrict__ v_up,
             int m)
{
    combine_proj_body(bias_in, out, k_up, v_up, m, blockIdx.x, threadIdx.x);
}

__global__ void __launch_bounds__(256)
combine_proj_kv(const float* __restrict__ bk, const float* __restrict__ bv,
                float* __restrict__ k_up, float* __restrict__ v_up)
{
    const int m = 1 + (int)blockIdx.y;
    combine_proj_body((m == 1) ? bk : bv, nullptr, k_up, v_up, m,
                      blockIdx.x, threadIdx.x);
}

// ---------------------------------------------------------------------------
// cp.async helpers
// ---------------------------------------------------------------------------
__device__ __forceinline__ void cp_async16(unsigned int smem_addr, const void* gptr) {
    asm volatile("cp.async.cg.shared.global [%0], [%1], 16;\n"
                 :: "r"(smem_addr), "l"(gptr) : "memory");
}
__device__ __forceinline__ void cp_commit() {
    asm volatile("cp.async.commit_group;\n" ::: "memory");
}
__device__ __forceinline__ void cp_wait1() {
    asm volatile("cp.async.wait_group 1;\n" ::: "memory");
}

// ---------------------------------------------------------------------------
// Split-K fused attention + cache copy.
// K: LDG->regs, scores from registers, STG copy at commit (uniform).
// V: cp.async double-buffered smem; uniform LDS->STG copy phase before PV.
// Mask prefetched one chunk ahead.
// ---------------------------------------------------------------------------
__global__ void __launch_bounds__(256, 4)
attn_kernel(const float* __restrict__ cache_k, const float* __restrict__ cache_v,
            const int* __restrict__ mask,
            float* __restrict__ k_up, float* __restrict__ v_up)
{
    const int blk   = blockIdx.x;
    const int bh    = blk >> 3;
    const int split = blk & 7;
    const int b     = bh >> 4;

    __shared__ float Qst[16][68];      // [q][kk], pre-scaled by 1/8
    __shared__ float Vs[2][64][68];    // double-buffered V chunk
    __shared__ float Ss[64][20];       // [j][q]
    __shared__ float s_corr[16];
    __shared__ float s_red[128][8];

    const int t = threadIdx.x;

    for (int i = t; i < Qdim * DH; i += 256) {
        const int q  = i >> 6;
        const int kk = i & 63;
        Qst[q][kk] = g_q_heads[(size_t)(bh * Qdim + q) * DH + kk] * 0.125f;
    }

    const int lj = t >> 2;           // 0..63 KV row for load/copy/scores
    const int g  = t & 3;            // k-slice: kk = g*4 + e*16

    const int row    = t >> 4;       // softmax role
    const int lane16 = t & 15;

    const int js  = t >> 7;          // PV: j parity
    const int rr  = (t >> 3) & 15;   // PV: row
    const int dhg = t & 7;           // PV: dh-group

    float m_i = -1e30f, l_i = 0.f;
    unsigned long long a0 = 0ull, a1 = 0ull, a2 = 0ull, a3 = 0ull;

    const float* Kb = cache_k + (size_t)bh * Cdim * DH;
    const float* Vb = cache_v + (size_t)bh * Cdim * DH;
    float* Kout = k_up + (size_t)bh * KLEN * DH;
    float* Vout = v_up + (size_t)bh * KLEN * DH;
    const int* Mb = mask + (size_t)b * Qdim * KLEN;

    float4 kf[4];
    int mcur[4], mnext[4];
    int cur = 0;

    auto prefetch_k = [&](int c) {
        if (c < 64) {
#pragma unroll
            for (int e = 0; e < 4; e++)
                kf[e] = *(const float4*)&Kb[((size_t)(c * 64 + lj)) * DH + g * 4 + e * 16];
        } else if (lj < 16) {
#pragma unroll
            for (int e = 0; e < 4; e++)
                kf[e] = *(const float4*)&Kout[((size_t)(Cdim + lj)) * DH + g * 4 + e * 16];
        }
    };

    auto prefetch_mask = [&](int c, int* mr) {
        const int cb = (c < 64) ? 64 : 16;
#pragma unroll
        for (int e = 0; e < 4; e++) {
            const int j = lane16 + e * 16;
            mr[e] = (j < cb) ? Mb[row * KLEN + c * 64 + j] : 0;
        }
    };

    // issue V cp.async for chunk c into buffer buf (always commits a group)
    auto issue_v = [&](int c, int buf) {
        if (c < 64) {
#pragma unroll
            for (int e = 0; e < 4; e++) {
                const int kk = g * 4 + e * 16;
                unsigned int sa = (unsigned int)__cvta_generic_to_shared(&Vs[buf][lj][kk]);
                cp_async16(sa, &Vb[((size_t)(c * 64 + lj)) * DH + kk]);
            }
        } else if (c == 64) {
            if (lj < 16) {
#pragma unroll
                for (int e = 0; e < 4; e++) {
                    const int kk = g * 4 + e * 16;
                    unsigned int sa = (unsigned int)__cvta_generic_to_shared(&Vs[buf][lj][kk]);
                    cp_async16(sa, &Vout[((size_t)(Cdim + lj)) * DH + kk]);
                }
            } else {
#pragma unroll
                for (int e = 0; e < 4; e++)
                    *(float4*)&Vs[buf][lj][g * 4 + e * 16] = make_float4(0.f, 0.f, 0.f, 0.f);
            }
        }
        cp_commit();
    };

    prefetch_k(split);
    prefetch_mask(split, mcur);
    issue_v(split, 0);

    for (int c = split; c < 65; c += NSPLIT) {
        const int kvBase = c * 64;
        const bool full  = (c < 64);

        __syncthreads();   // prev PV done; Vs[cur^1] free; Ss reusable

        // K cache copy (from registers, uniform across warps)
        if (full) {
#pragma unroll
            for (int e = 0; e < 4; e++)
                *(float4*)&Kout[((size_t)(kvBase + lj)) * DH + g * 4 + e * 16] = kf[e];
        }

        // start V load for the next chunk into the other buffer
        issue_v(c + NSPLIT, cur ^ 1);

        // --- scores from K registers: 2 passes of 8 queries ---
#pragma unroll
        for (int p = 0; p < 2; p++) {
            float s[8];
#pragma unroll
            for (int q = 0; q < 8; q++) s[q] = 0.f;
#pragma unroll
            for (int e = 0; e < 4; e++) {
                const float4 kv = kf[e];
#pragma unroll
                for (int q = 0; q < 8; q++) {
                    float4 qv = *(const float4*)&Qst[p * 8 + q][g * 4 + e * 16];
                    s[q] += qv.x * kv.x + qv.y * kv.y + qv.z * kv.z + qv.w * kv.w;
                }
            }
#pragma unroll
            for (int mk = 1; mk <= 2; mk <<= 1)
#pragma unroll
                for (int q = 0; q < 8; q++)
                    s[q] += __shfl_xor_sync(0xffffffffu, s[q], mk);
            *(float2*)&Ss[lj][p * 8 + g * 2] = make_float2(s[g * 2], s[g * 2 + 1]);
        }

        // prefetch K + mask for next chunk (covered by softmax + PV below)
        if (c + NSPLIT < 65) {
            prefetch_k(c + NSPLIT);
            prefetch_mask(c + NSPLIT, mnext);
        }

        __syncthreads();   // Ss ready

        // --- online softmax ---
        {
            float sv[4];
            float mx = -1e30f;
#pragma unroll
            for (int e = 0; e < 4; e++) {
                float s = Ss[lane16 + e * 16][row];
                if (mcur[e] == 0) s = -1e9f;
                sv[e] = s;
                mx = fmaxf(mx, s);
            }
#pragma unroll
            for (int off = 8; off; off >>= 1)
                mx = fmaxf(mx, __shfl_xor_sync(0xffffffffu, mx, off));
            const float m_new = fmaxf(m_i, mx);
            const float corr  = __expf(m_i - m_new);
            float lsum = 0.f;
#pragma unroll
            for (int e = 0; e < 4; e++) {
                const float p = __expf(sv[e] - m_new);
                Ss[lane16 + e * 16][row] = p;
                lsum += p;
            }
#pragma unroll
            for (int off = 8; off; off >>= 1)
                lsum += __shfl_xor_sync(0xffffffffu, lsum, off);
            l_i = l_i * corr + lsum;
            m_i = m_new;
            if (lane16 == 0) s_corr[row] = corr;
        }

        cp_wait1();        // current chunk's V resident
        __syncthreads();   // probs + corr + Vs[cur] visible

        // --- uniform V cache copy: thread copies row lj, cols g*4+e*16 ---
        if (full) {
#pragma unroll
            for (int e = 0; e < 4; e++) {
                const int kk = g * 4 + e * 16;
                float4 vv = *(const float4*)&Vs[cur][lj][kk];
                *(float4*)&Vout[((size_t)(kvBase + lj)) * DH + kk] = vv;
            }
        }

        // --- PV: packed FFMA2 over 64 keys ---
        {
            const float corr_v = s_corr[rr];
            unsigned long long corr2;
            asm("mov.b64 %0, {%1, %1};" : "=l"(corr2) : "f"(corr_v));
            asm("mul.rn.f32x2 %0, %0, %1;" : "+l"(a0) : "l"(corr2));
            asm("mul.rn.f32x2 %0, %0, %1;" : "+l"(a1) : "l"(corr2));
            asm("mul.rn.f32x2 %0, %0, %1;" : "+l"(a2) : "l"(corr2));
            asm("mul.rn.f32x2 %0, %0, %1;" : "+l"(a3) : "l"(corr2));
#pragma unroll 8
            for (int j = js; j < 64; j += 2) {
                const float p = Ss[j][rr];
                unsigned long long p2;
                asm("mov.b64 %0, {%1, %1};" : "=l"(p2) : "f"(p));
                ulonglong2 v0 = *reinterpret_cast<const ulonglong2*>(&Vs[cur][j][dhg * 4]);
                ulonglong2 v1 = *reinterpret_cast<const ulonglong2*>(&Vs[cur][j][32 + dhg * 4]);
                asm("fma.rn.f32x2 %0, %1, %2, %0;" : "+l"(a0) : "l"(v0.x), "l"(p2));
                asm("fma.rn.f32x2 %0, %1, %2, %0;" : "+l"(a1) : "l"(v0.y), "l"(p2));
                asm("fma.rn.f32x2 %0, %1, %2, %0;" : "+l"(a2) : "l"(v1.x), "l"(p2));
                asm("fma.rn.f32x2 %0, %1, %2, %0;" : "+l"(a3) : "l"(v1.y), "l"(p2));
            }
        }

#pragma unroll
        for (int e = 0; e < 4; e++) mcur[e] = mnext[e];
        cur ^= 1;
    }

    if (lane16 == 0)
        g_part_ml[(bh * NSPLIT + split) * Qdim + row] = make_float2(m_i, l_i);

    float f0, f1, f2, f3, f4, f5, f6, f7;
    asm("mov.b64 {%0, %1}, %2;" : "=f"(f0), "=f"(f1) : "l"(a0));
    asm("mov.b64 {%0, %1}, %2;" : "=f"(f2), "=f"(f3) : "l"(a1));
    asm("mov.b64 {%0, %1}, %2;" : "=f"(f4), "=f"(f5) : "l"(a2));
    asm("mov.b64 {%0, %1}, %2;" : "=f"(f6), "=f"(f7) : "l"(a3));

    if (js == 1) {
        float* r = s_red[t - 128];
        r[0] = f0; r[1] = f1; r[2] = f2; r[3] = f3;
        r[4] = f4; r[5] = f5; r[6] = f6; r[7] = f7;
    }
    __syncthreads();
    if (js == 0) {
        const float* r = s_red[t];
        const size_t base = ((size_t)(bh * NSPLIT + split) * Qdim + rr) * DH;
        float4 o0 = make_float4(f0 + r[0], f1 + r[1], f2 + r[2], f3 + r[3]);
        float4 o1 = make_float4(f4 + r[4], f5 + r[5], f6 + r[6], f7 + r[7]);
        *(float4*)&g_part_acc[base + dhg * 4]      = o0;
        *(float4*)&g_part_acc[base + 32 + dhg * 4] = o1;
    }
}

// ---------------------------------------------------------------------------
// Combine attention split partials -> g_attn_x
// ---------------------------------------------------------------------------
__global__ void __launch_bounds__(256)
combine_kernel()
{
    const int bh  = blockIdx.x;
    const int t   = threadIdx.x;
    const int row = t >> 4;
    const int dh0 = (t & 15) * 4;

    float2 ml[NSPLIT];
    float m = -1e30f;
#pragma unroll
    for (int s = 0; s < NSPLIT; s++) {
        ml[s] = g_part_ml[(bh * NSPLIT + s) * Qdim + row];
        m = fmaxf(m, ml[s].x);
    }
    float l = 0.f;
    float4 o = make_float4(0.f, 0.f, 0.f, 0.f);
#pragma unroll
    for (int s = 0; s < NSPLIT; s++) {
        const float w = __expf(ml[s].x - m);
        l += ml[s].y * w;
        float4 a = *(const float4*)&g_part_acc[((size_t)(bh * NSPLIT + s) * Qdim + row) * DH + dh0];
        o.x += a.x * w; o.y += a.y * w; o.z += a.z * w; o.w += a.w * w;
    }
    const float inv = 1.f / l;
    const int b = bh >> 4;
    const int h = bh & 15;
    o.x *= inv; o.y *= inv; o.z *= inv; o.w *= inv;
    *(float4*)&g_attn_x[(size_t)(b * Qdim + row) * Ddim + h * DH + dh0] = o;
}

// ---------------------------------------------------------------------------
extern "C" void kernel_launch(void* const* d_in, const int* in_sizes, int n_in,
                              void* d_out, int out_size)
{
    const float* query   = (const float*)d_in[0];
    const float* key     = (const float*)d_in[1];
    const float* value   = (const float*)d_in[2];
    const int*   mask    = (const int*)d_in[3];
    const float* cache_k = (const float*)d_in[4];
    const float* cache_v = (const float*)d_in[5];
    const float* Wq = (const float*)d_in[6];
    const float* bq = (const float*)d_in[7];
    const float* Wk = (const float*)d_in[8];
    const float* bk = (const float*)d_in[9];
    const float* Wv = (const float*)d_in[10];
    const float* bv = (const float*)d_in[11];
    const float* Wo = (const float*)d_in[12];
    const float* bo = (const float*)d_in[13];

    float* out  = (float*)d_out;
    float* k_up = out + (size_t)Bdim * Qdim * Ddim;
    float* v_up = k_up + (size_t)Bdim * Hdim * KLEN * DH;

    // launches 1-3 (attn_kernel is the 4th launch — ncu hits #4)
    proj_kernel<<<dim3(4, 16, 3 * KS), 256>>>(query, key, value, Wq, Wk, Wv, 0);
    combine_proj<<<ROWS, 256>>>(bq, out, k_up, v_up, 0);
    combine_proj_kv<<<dim3(ROWS, 2), 256>>>(bk, bv, k_up, v_up);

    // 4: attention
    attn_kernel<<<Bdim * Hdim * NSPLIT, 256>>>(cache_k, cache_v, mask, k_up, v_up);

    combine_kernel<<<Bdim * Hdim, 256>>>();

    proj_kernel<<<dim3(4, 16, KS), 256>>>(nullptr, nullptr, nullptr, Wo, nullptr, nullptr, 1);
    combine_proj<<<ROWS, 256>>>(bo, out, k_up, v_up, 3);
}

// round 10
// speedup vs baseline: 1.8255x; 1.2502x over previous
#include <cuda_runtime.h>
#include <cstddef>
#include <cstdint>

// ---------------------------------------------------------------------------
// MultiHeadedAttentionWithCache  (B=16,Q=16,D=1024,H=16,DH=64,C=4096,KLEN=4112)
// d_out = concat(out[16,16,1024], k_up[16,16,4112,64], v_up[16,16,4112,64])
// ---------------------------------------------------------------------------

#define Bdim 16
#define Qdim 16
#define Ddim 1024
#define Hdim 16
#define DH   64
#define Cdim 4096
#define KLEN 4112
#define ROWS 256
#define NSPLIT 8
#define KS 4

__device__ float  g_q_heads[ROWS * Ddim];
__device__ float  g_attn_x[ROWS * Ddim];
__device__ float  g_part_acc[256 * NSPLIT * Qdim * DH];
__device__ float2 g_part_ml[256 * NSPLIT * Qdim];
__device__ float  g_proj_part[3 * KS * ROWS * Ddim];

// ---------------------------------------------------------------------------
// Projection GEMM, split-K
// ---------------------------------------------------------------------------
#define BM 64
#define BN 64
#define BK 16

__global__ void __launch_bounds__(256)
proj_kernel(const float* __restrict__ Aq, const float* __restrict__ Ak,
            const float* __restrict__ Av,
            const float* __restrict__ Wq, const float* __restrict__ Wk,
            const float* __restrict__ Wv,
            int mode_base)
{
    const int zz = blockIdx.z;
    const int m  = mode_base ? 3 : (zz / KS);
    const int ks = mode_base ? zz : (zz % KS);
    const int mslot = (m == 3) ? 0 : m;

    const float* A = (m == 0) ? Aq : (m == 1) ? Ak : (m == 2) ? Av : g_attn_x;
    const float* W = (m == 1) ? Wk : (m == 2) ? Wv : Wq;

    __shared__ float As[BK][BM + 4];
    __shared__ float Bs[BK][BN];

    const int rowBase = blockIdx.x * BM;
    const int colBase = blockIdx.y * BN;

    const int t  = threadIdx.x;
    const int tx = t & 15;
    const int ty = t >> 4;

    float acc[4][4];
#pragma unroll
    for (int i = 0; i < 4; i++)
#pragma unroll
        for (int j = 0; j < 4; j++) acc[i][j] = 0.f;

    const int la_r  = t & 63;
    const int la_k4 = (t >> 6) * 4;
    const int lb_k  = t >> 4;
    const int lb_c4 = (t & 15) * 4;

    const int k0 = ks * (Ddim / KS);

    for (int kt = k0; kt < k0 + Ddim / KS; kt += BK) {
        float4 a4 = *(const float4*)&A[(size_t)(rowBase + la_r) * Ddim + kt + la_k4];
        As[la_k4 + 0][la_r] = a4.x;
        As[la_k4 + 1][la_r] = a4.y;
        As[la_k4 + 2][la_r] = a4.z;
        As[la_k4 + 3][la_r] = a4.w;
        *(float4*)&Bs[lb_k][lb_c4] =
            *(const float4*)&W[(size_t)(kt + lb_k) * Ddim + colBase + lb_c4];
        __syncthreads();
#pragma unroll
        for (int kk = 0; kk < BK; kk++) {
            float ar[4], br[4];
            *(float4*)ar = *(const float4*)&As[kk][ty * 4];
            *(float4*)br = *(const float4*)&Bs[kk][tx * 4];
#pragma unroll
            for (int i = 0; i < 4; i++)
#pragma unroll
                for (int j = 0; j < 4; j++)
                    acc[i][j] += ar[i] * br[j];
        }
        __syncthreads();
    }

    float* P = g_proj_part + (size_t)(mslot * KS + ks) * ROWS * Ddim;
#pragma unroll
    for (int i = 0; i < 4; i++) {
        const int row = rowBase + ty * 4 + i;
        float4 v = make_float4(acc[i][0], acc[i][1], acc[i][2], acc[i][3]);
        *(float4*)&P[(size_t)row * Ddim + colBase + tx * 4] = v;
    }
}

// ---------------------------------------------------------------------------
// Combine split-K proj partials + bias + scatter
// ---------------------------------------------------------------------------
__device__ __forceinline__ void combine_proj_body(
    const float* __restrict__ bias_in,
    float* __restrict__ out,
    float* __restrict__ k_up, float* __restrict__ v_up,
    int m, int row, int t)
{
    const int mslot = (m == 3) ? 0 : m;
    const int col = t * 4;

    const float* P = g_proj_part + (size_t)(mslot * KS) * ROWS * Ddim
                   + (size_t)row * Ddim + col;
    float4 s = *(const float4*)&P[0];
#pragma unroll
    for (int ksl = 1; ksl < KS; ksl++) {
        float4 p = *(const float4*)&P[(size_t)ksl * ROWS * Ddim];
        s.x += p.x; s.y += p.y; s.z += p.z; s.w += p.w;
    }
    float4 bb = *(const float4*)&bias_in[col];
    s.x += bb.x; s.y += bb.y; s.z += bb.z; s.w += bb.w;

    const int b  = row >> 4;
    const int qi = row & 15;
    const int h  = col >> 6;
    const int dh = col & 63;

    if (m == 0) {
        *(float4*)&g_q_heads[(size_t)((b * Hdim + h) * Qdim + qi) * DH + dh] = s;
    } else if (m == 1) {
        *(float4*)&k_up[((size_t)(b * Hdim + h) * KLEN + Cdim + qi) * DH + dh] = s;
    } else if (m == 2) {
        *(float4*)&v_up[((size_t)(b * Hdim + h) * KLEN + Cdim + qi) * DH + dh] = s;
    } else {
        *(float4*)&out[(size_t)row * Ddim + col] = s;
    }
}

__global__ void __launch_bounds__(256)
combine_proj(const float* __restrict__ bias_in,
             float* __restrict__ out,
             float* __restrict__ k_up, float* __restrict__ v_up,
             int m)
{
    combine_proj_body(bias_in, out, k_up, v_up, m, blockIdx.x, threadIdx.x);
}

__global__ void __launch_bounds__(256)
combine_proj_kv(const float* __restrict__ bk, const float* __restrict__ bv,
                float* __restrict__ k_up, float* __restrict__ v_up)
{
    const int m = 1 + (int)blockIdx.y;
    combine_proj_body((m == 1) ? bk : bv, nullptr, k_up, v_up, m,
                      blockIdx.x, threadIdx.x);
}

// ---------------------------------------------------------------------------
// cp.async helpers
// ---------------------------------------------------------------------------
__device__ __forceinline__ void cp_async16(unsigned int smem_addr, const void* gptr) {
    asm volatile("cp.async.cg.shared.global [%0], [%1], 16;\n"
                 :: "r"(smem_addr), "l"(gptr) : "memory");
}
__device__ __forceinline__ void cp_commit() {
    asm volatile("cp.async.commit_group;\n" ::: "memory");
}
__device__ __forceinline__ void cp_wait1() {
    asm volatile("cp.async.wait_group 1;\n" ::: "memory");
}

// ---------------------------------------------------------------------------
// Split-K fused attention + cache copy — L1tex-byte-optimized.
// Scores: thread owns 2 K rows (lj, lj+32), 8-float kk slice; Q LDS reused
//         across both rows; 8-lane shfl reduce. Ss layout [q][j].
// PV: thread = (js, q-pair, dh-quad); P via LDS.128; V read once per 2 q.
// Mask: int4; softmax vectorized LDS/STS.128.
// ---------------------------------------------------------------------------
__global__ void __launch_bounds__(256, 4)
attn_kernel(const float* __restrict__ cache_k, const float* __restrict__ cache_v,
            const int* __restrict__ mask,
            float* __restrict__ k_up, float* __restrict__ v_up)
{
    const int blk   = blockIdx.x;
    const int bh    = blk >> 3;
    const int split = blk & 7;
    const int b     = bh >> 4;

    __shared__ float Qst[16][68];      // [q][kk] pre-scaled by 1/8
    __shared__ float Vs[2][64][68];    // double-buffered V chunk [j][dh]
    __shared__ float Ss[16][68];       // [q][j] scores -> probabilities
    __shared__ float s_corr[16];
    __shared__ float s_red[128][8];

    const int t = threadIdx.x;

    for (int i = t; i < Qdim * DH; i += 256) {
        const int q  = i >> 6;
        const int kk = i & 63;
        Qst[q][kk] = g_q_heads[(size_t)(bh * Qdim + q) * DH + kk] * 0.125f;
    }

    const int lj = t >> 3;           // 0..31 : K/V rows lj and lj+32
    const int gg = t & 7;            // kk slice: gg*4 and gg*4+32

    const int row = t >> 4;          // softmax role: query row
    const int j4  = (t & 15) * 4;    // softmax role: 4 j's

    const int js  = t >> 7;          // PV: j half
    const int qg  = (t >> 4) & 7;    // PV: query pair
    const int dh4 = t & 15;          // PV: dh quad

    float m_i = -1e30f, l_i = 0.f;
    // acc0,acc1 = query q0 dh[dh4*4..+3]; acc2,acc3 = query q1
    unsigned long long a0 = 0ull, a1 = 0ull, a2 = 0ull, a3 = 0ull;

    const float* Kb = cache_k + (size_t)bh * Cdim * DH;
    const float* Vb = cache_v + (size_t)bh * Cdim * DH;
    float* Kout = k_up + (size_t)bh * KLEN * DH;
    float* Vout = v_up + (size_t)bh * KLEN * DH;
    const int* Mb = mask + (size_t)b * Qdim * KLEN;

    float4 kf[4];    // [row r][slice e]: kf[r*2+e]
    int4 mcur, mnext;
    int cur = 0;

    auto prefetch_k = [&](int c) {
        if (c < 64) {
            const float* p0 = &Kb[((size_t)(c * 64 + lj)) * DH + gg * 4];
            kf[0] = *(const float4*)p0;
            kf[1] = *(const float4*)(p0 + 32);
            const float* p1 = p0 + 32 * DH;
            kf[2] = *(const float4*)p1;
            kf[3] = *(const float4*)(p1 + 32);
        } else {
            const float4 z = make_float4(0.f, 0.f, 0.f, 0.f);
            if (lj < 16) {
                const float* p0 = &Kout[((size_t)(Cdim + lj)) * DH + gg * 4];
                kf[0] = *(const float4*)p0;
                kf[1] = *(const float4*)(p0 + 32);
            } else { kf[0] = z; kf[1] = z; }
            kf[2] = z; kf[3] = z;
        }
    };

    auto prefetch_mask = [&](int c, int4& mr) {
        if (c < 64 || j4 < 16)
            mr = *(const int4*)&Mb[row * KLEN + c * 64 + j4];
        else
            mr = make_int4(0, 0, 0, 0);
    };

    auto issue_v = [&](int c, int buf) {
        if (c < 64) {
            const float* p0 = &Vb[((size_t)(c * 64 + lj)) * DH + gg * 4];
            cp_async16((unsigned int)__cvta_generic_to_shared(&Vs[buf][lj][gg * 4]), p0);
            cp_async16((unsigned int)__cvta_generic_to_shared(&Vs[buf][lj][gg * 4 + 32]), p0 + 32);
            const float* p1 = p0 + 32 * DH;
            cp_async16((unsigned int)__cvta_generic_to_shared(&Vs[buf][lj + 32][gg * 4]), p1);
            cp_async16((unsigned int)__cvta_generic_to_shared(&Vs[buf][lj + 32][gg * 4 + 32]), p1 + 32);
        } else if (c == 64) {
            const float4 z = make_float4(0.f, 0.f, 0.f, 0.f);
            if (lj < 16) {
                const float* p0 = &Vout[((size_t)(Cdim + lj)) * DH + gg * 4];
                cp_async16((unsigned int)__cvta_generic_to_shared(&Vs[buf][lj][gg * 4]), p0);
                cp_async16((unsigned int)__cvta_generic_to_shared(&Vs[buf][lj][gg * 4 + 32]), p0 + 32);
            } else {
                *(float4*)&Vs[buf][lj][gg * 4] = z;
                *(float4*)&Vs[buf][lj][gg * 4 + 32] = z;
            }
            *(float4*)&Vs[buf][lj + 32][gg * 4] = z;
            *(float4*)&Vs[buf][lj + 32][gg * 4 + 32] = z;
        }
        cp_commit();
    };

    prefetch_k(split);
    prefetch_mask(split, mcur);
    issue_v(split, 0);

    for (int c = split; c < 65; c += NSPLIT) {
        const int kvBase = c * 64;
        const bool full  = (c < 64);

        __syncthreads();   // prev PV done; Vs[cur^1] free; Ss writable

        // K cache copy (from registers)
        if (full) {
            float* d0 = &Kout[((size_t)(kvBase + lj)) * DH + gg * 4];
            *(float4*)d0 = kf[0];
            *(float4*)(d0 + 32) = kf[1];
            float* d1 = d0 + 32 * DH;
            *(float4*)d1 = kf[2];
            *(float4*)(d1 + 32) = kf[3];
        }

        // start V load for next chunk into other buffer
        issue_v(c + NSPLIT, cur ^ 1);

        // --- scores: 2 passes of 8 queries, 2 K rows per thread ---
#pragma unroll
        for (int p = 0; p < 2; p++) {
            float s[16];
#pragma unroll
            for (int i = 0; i < 16; i++) s[i] = 0.f;
#pragma unroll
            for (int e = 0; e < 2; e++) {
                const float4 k0 = kf[e];
                const float4 k1 = kf[2 + e];
#pragma unroll
                for (int ql = 0; ql < 8; ql++) {
                    float4 qv = *(const float4*)&Qst[p * 8 + ql][gg * 4 + e * 32];
                    s[ql * 2 + 0] += qv.x * k0.x + qv.y * k0.y + qv.z * k0.z + qv.w * k0.w;
                    s[ql * 2 + 1] += qv.x * k1.x + qv.y * k1.y + qv.z * k1.z + qv.w * k1.w;
                }
            }
#pragma unroll
            for (int off = 1; off <= 4; off <<= 1)
#pragma unroll
                for (int i = 0; i < 16; i++)
                    s[i] += __shfl_xor_sync(0xffffffffu, s[i], off);
            // lane gg keeps query p*8+gg
            Ss[p * 8 + gg][lj]      = s[gg * 2 + 0];
            Ss[p * 8 + gg][lj + 32] = s[gg * 2 + 1];
        }

        // prefetch K + mask for next chunk
        if (c + NSPLIT < 65) {
            prefetch_k(c + NSPLIT);
            prefetch_mask(c + NSPLIT, mnext);
        }

        __syncthreads();   // Ss scores ready

        // --- online softmax (vectorized) ---
        {
            float4 sv = *(const float4*)&Ss[row][j4];
            if (mcur.x == 0) sv.x = -1e9f;
            if (mcur.y == 0) sv.y = -1e9f;
            if (mcur.z == 0) sv.z = -1e9f;
            if (mcur.w == 0) sv.w = -1e9f;
            float mx = fmaxf(fmaxf(sv.x, sv.y), fmaxf(sv.z, sv.w));
#pragma unroll
            for (int off = 8; off; off >>= 1)
                mx = fmaxf(mx, __shfl_xor_sync(0xffffffffu, mx, off));
            const float m_new = fmaxf(m_i, mx);
            const float corr  = __expf(m_i - m_new);
            float4 pv;
            pv.x = __expf(sv.x - m_new);
            pv.y = __expf(sv.y - m_new);
            pv.z = __expf(sv.z - m_new);
            pv.w = __expf(sv.w - m_new);
            *(float4*)&Ss[row][j4] = pv;
            float lsum = pv.x + pv.y + pv.z + pv.w;
#pragma unroll
            for (int off = 8; off; off >>= 1)
                lsum += __shfl_xor_sync(0xffffffffu, lsum, off);
            l_i = l_i * corr + lsum;
            m_i = m_new;
            if ((t & 15) == 0) s_corr[row] = corr;
        }

        cp_wait1();        // current chunk's V resident
        __syncthreads();   // probs + corr + Vs[cur] visible

        // --- uniform V cache copy ---
        if (full) {
            float* d0 = &Vout[((size_t)(kvBase + lj)) * DH + gg * 4];
            *(float4*)d0        = *(const float4*)&Vs[cur][lj][gg * 4];
            *(float4*)(d0 + 32) = *(const float4*)&Vs[cur][lj][gg * 4 + 32];
            float* d1 = d0 + 32 * DH;
            *(float4*)d1        = *(const float4*)&Vs[cur][lj + 32][gg * 4];
            *(float4*)(d1 + 32) = *(const float4*)&Vs[cur][lj + 32][gg * 4 + 32];
        }

        // --- PV: (js, q-pair qg, dh-quad dh4) ---
        {
            const int q0 = qg * 2;
            const float c0 = s_corr[q0];
            const float c1 = s_corr[q0 + 1];
            unsigned long long cc0, cc1;
            asm("mov.b64 %0, {%1, %1};" : "=l"(cc0) : "f"(c0));
            asm("mov.b64 %0, {%1, %1};" : "=l"(cc1) : "f"(c1));
            asm("mul.rn.f32x2 %0, %0, %1;" : "+l"(a0) : "l"(cc0));
            asm("mul.rn.f32x2 %0, %0, %1;" : "+l"(a1) : "l"(cc0));
            asm("mul.rn.f32x2 %0, %0, %1;" : "+l"(a2) : "l"(cc1));
            asm("mul.rn.f32x2 %0, %0, %1;" : "+l"(a3) : "l"(cc1));
            const int jBase = js * 32;
#pragma unroll 4
            for (int j = jBase; j < jBase + 32; j += 4) {
                float4 p0 = *(const float4*)&Ss[q0][j];
                float4 p1 = *(const float4*)&Ss[q0 + 1][j];
                float pa0[4] = {p0.x, p0.y, p0.z, p0.w};
                float pa1[4] = {p1.x, p1.y, p1.z, p1.w};
#pragma unroll
                for (int u = 0; u < 4; u++) {
                    ulonglong2 vv = *reinterpret_cast<const ulonglong2*>(&Vs[cur][j + u][dh4 * 4]);
                    unsigned long long pp0, pp1;
                    asm("mov.b64 %0, {%1, %1};" : "=l"(pp0) : "f"(pa0[u]));
                    asm("mov.b64 %0, {%1, %1};" : "=l"(pp1) : "f"(pa1[u]));
                    asm("fma.rn.f32x2 %0, %1, %2, %0;" : "+l"(a0) : "l"(vv.x), "l"(pp0));
                    asm("fma.rn.f32x2 %0, %1, %2, %0;" : "+l"(a1) : "l"(vv.y), "l"(pp0));
                    asm("fma.rn.f32x2 %0, %1, %2, %0;" : "+l"(a2) : "l"(vv.x), "l"(pp1));
                    asm("fma.rn.f32x2 %0, %1, %2, %0;" : "+l"(a3) : "l"(vv.y), "l"(pp1));
                }
            }
        }

        mcur = mnext;
        cur ^= 1;
    }

    if ((t & 15) == 0)
        g_part_ml[(bh * NSPLIT + split) * Qdim + row] = make_float2(m_i, l_i);

    float f0, f1, f2, f3, f4, f5, f6, f7;
    asm("mov.b64 {%0, %1}, %2;" : "=f"(f0), "=f"(f1) : "l"(a0));
    asm("mov.b64 {%0, %1}, %2;" : "=f"(f2), "=f"(f3) : "l"(a1));
    asm("mov.b64 {%0, %1}, %2;" : "=f"(f4), "=f"(f5) : "l"(a2));
    asm("mov.b64 {%0, %1}, %2;" : "=f"(f6), "=f"(f7) : "l"(a3));

    if (js == 1) {
        float* r = s_red[t - 128];
        r[0] = f0; r[1] = f1; r[2] = f2; r[3] = f3;
        r[4] = f4; r[5] = f5; r[6] = f6; r[7] = f7;
    }
    __syncthreads();
    if (js == 0) {
        const float* r = s_red[t];
        const int q0 = qg * 2;
        const size_t base = ((size_t)(bh * NSPLIT + split) * Qdim) * DH;
        float4 o0 = make_float4(f0 + r[0], f1 + r[1], f2 + r[2], f3 + r[3]);
        float4 o1 = make_float4(f4 + r[4], f5 + r[5], f6 + r[6], f7 + r[7]);
        *(float4*)&g_part_acc[base + (size_t)q0 * DH + dh4 * 4]       = o0;
        *(float4*)&g_part_acc[base + (size_t)(q0 + 1) * DH + dh4 * 4] = o1;
    }
}

// ---------------------------------------------------------------------------
// Combine attention split partials -> g_attn_x
// ---------------------------------------------------------------------------
__global__ void __launch_bounds__(256)
combine_kernel()
{
    const int bh  = blockIdx.x;
    const int t   = threadIdx.x;
    const int row = t >> 4;
    const int dh0 = (t & 15) * 4;

    float2 ml[NSPLIT];
    float m = -1e30f;
#pragma unroll
    for (int s = 0; s < NSPLIT; s++) {
        ml[s] = g_part_ml[(bh * NSPLIT + s) * Qdim + row];
        m = fmaxf(m, ml[s].x);
    }
    float l = 0.f;
    float4 o = make_float4(0.f, 0.f, 0.f, 0.f);
#pragma unroll
    for (int s = 0; s < NSPLIT; s++) {
        const float w = __expf(ml[s].x - m);
        l += ml[s].y * w;
        float4 a = *(const float4*)&g_part_acc[((size_t)(bh * NSPLIT + s) * Qdim + row) * DH + dh0];
        o.x += a.x * w; o.y += a.y * w; o.z += a.z * w; o.w += a.w * w;
    }
    const float inv = 1.f / l;
    const int b = bh >> 4;
    const int h = bh & 15;
    o.x *= inv; o.y *= inv; o.z *= inv; o.w *= inv;
    *(float4*)&g_attn_x[(size_t)(b * Qdim + row) * Ddim + h * DH + dh0] = o;
}

// ---------------------------------------------------------------------------
extern "C" void kernel_launch(void* const* d_in, const int* in_sizes, int n_in,
                              void* d_out, int out_size)
{
    const float* query   = (const float*)d_in[0];
    const float* key     = (const float*)d_in[1];
    const float* value   = (const float*)d_in[2];
    const int*   mask    = (const int*)d_in[3];
    const float* cache_k = (const float*)d_in[4];
    const float* cache_v = (const float*)d_in[5];
    const float* Wq = (const float*)d_in[6];
    const float* bq = (const float*)d_in[7];
    const float* Wk = (const float*)d_in[8];
    const float* bk = (const float*)d_in[9];
    const float* Wv = (const float*)d_in[10];
    const float* bv = (const float*)d_in[11];
    const float* Wo = (const float*)d_in[12];
    const float* bo = (const float*)d_in[13];

    float* out  = (float*)d_out;
    float* k_up = out + (size_t)Bdim * Qdim * Ddim;
    float* v_up = k_up + (size_t)Bdim * Hdim * KLEN * DH;

    // launches 1-3 (attn_kernel is the 4th launch — ncu hits #4)
    proj_kernel<<<dim3(4, 16, 3 * KS), 256>>>(query, key, value, Wq, Wk, Wv, 0);
    combine_proj<<<ROWS, 256>>>(bq, out, k_up, v_up, 0);
    combine_proj_kv<<<dim3(ROWS, 2), 256>>>(bk, bv, k_up, v_up);

    // 4: attention
    attn_kernel<<<Bdim * Hdim * NSPLIT, 256>>>(cache_k, cache_v, mask, k_up, v_up);

    combine_kernel<<<Bdim * Hdim, 256>>>();

    proj_kernel<<<dim3(4, 16, KS), 256>>>(nullptr, nullptr, nullptr, Wo, nullptr, nullptr, 1);
    combine_proj<<<ROWS, 256>>>(bo, out, k_up, v_up, 3);
}